// round 1
// baseline (speedup 1.0000x reference)
#include <cuda_runtime.h>

#define TT 1024
#define HH 16
#define SS 8192
#define DK 192      // 128 (absorbed nope) + 64 (rope)
#define DV 128
#define LORA 512
#define KV_W 576
#define SCALING 0.07216878364870322f  // 1/sqrt(192)

// Per-head effective K (lora-absorbed 128 dims + rope 64 dims) and V.
__device__ float g_K[HH * SS * DK];   // ~100.7 MB
__device__ float g_V[HH * SS * DV];   // ~67.1 MB

// ---------------------------------------------------------------------------
// Projection GEMMs:
//  MODE 0: g_K[h,s,j] = sum_l kv[s,l] * w_kc[h,j,l]  (j<128), plus rope copy
//  MODE 1: g_V[h,s,j] = sum_l kv[s,l] * w_vc[h,l,j]
// Tile: 128(s) x 128(j), K-chunks of 16, 256 threads, 8x8 per thread.
// ---------------------------------------------------------------------------
template<int MODE>
__global__ __launch_bounds__(256)
void proj_kernel(const float* __restrict__ kv, const float* __restrict__ w) {
    __shared__ float As[16 * 132];   // [k][m], padded
    __shared__ float Bs[16 * 128];   // [k][j]
    const int h  = blockIdx.y;
    const int s0 = blockIdx.x * 128;
    const int tid = threadIdx.x;
    const int ty = tid >> 4, tx = tid & 15;
    const int m0 = ty * 8, n0 = tx * 8;

    float acc[8][8];
    #pragma unroll
    for (int i = 0; i < 8; i++)
        #pragma unroll
        for (int j = 0; j < 8; j++) acc[i][j] = 0.f;

    for (int kt = 0; kt < LORA; kt += 16) {
        // A tile (kv rows), stored transposed [k][m]
        {
            const int m  = tid >> 1;
            const int k8 = (tid & 1) * 8;
            const float* src = kv + (s0 + m) * KV_W + kt + k8;
            #pragma unroll
            for (int kk = 0; kk < 8; kk++) As[(k8 + kk) * 132 + m] = src[kk];
        }
        if (MODE == 0) {
            // w_kc[h, j, l]: contiguous in l (=k)
            const int j  = tid >> 1;
            const int k8 = (tid & 1) * 8;
            const float* src = w + h * (128 * 512) + j * 512 + kt + k8;
            #pragma unroll
            for (int kk = 0; kk < 8; kk++) Bs[(k8 + kk) * 128 + j] = src[kk];
        } else {
            // w_vc[h, l, j]: contiguous in j
            const int k  = tid >> 4;
            const int j8 = (tid & 15) * 8;
            const float* src = w + h * (512 * 128) + (kt + k) * 128 + j8;
            *(float4*)&Bs[k * 128 + j8]     = *(const float4*)src;
            *(float4*)&Bs[k * 128 + j8 + 4] = *(const float4*)(src + 4);
        }
        __syncthreads();
        #pragma unroll
        for (int k = 0; k < 16; k++) {
            float4 a0 = *(float4*)&As[k * 132 + m0];
            float4 a1 = *(float4*)&As[k * 132 + m0 + 4];
            float4 b0 = *(float4*)&Bs[k * 128 + n0];
            float4 b1 = *(float4*)&Bs[k * 128 + n0 + 4];
            float am[8] = {a0.x,a0.y,a0.z,a0.w,a1.x,a1.y,a1.z,a1.w};
            float bn[8] = {b0.x,b0.y,b0.z,b0.w,b1.x,b1.y,b1.z,b1.w};
            #pragma unroll
            for (int i = 0; i < 8; i++)
                #pragma unroll
                for (int j = 0; j < 8; j++) acc[i][j] += am[i] * bn[j];
        }
        __syncthreads();
    }

    if (MODE == 0) {
        #pragma unroll
        for (int i = 0; i < 8; i++) {
            float* dst = g_K + (h * SS + s0 + m0 + i) * DK + n0;
            #pragma unroll
            for (int j = 0; j < 8; j++) dst[j] = acc[i][j];
        }
        // rope passthrough: g_K[h,s,128+r] = kv[s,512+r]
        for (int idx = tid; idx < 128 * 64; idx += 256) {
            int m = idx >> 6, r = idx & 63;
            g_K[(h * SS + s0 + m) * DK + 128 + r] = kv[(s0 + m) * KV_W + 512 + r];
        }
    } else {
        #pragma unroll
        for (int i = 0; i < 8; i++) {
            float* dst = g_V + (h * SS + s0 + m0 + i) * DV + n0;
            #pragma unroll
            for (int j = 0; j < 8; j++) dst[j] = acc[i][j];
        }
    }
}

// ---------------------------------------------------------------------------
// Attention: per (head, 128-query tile). Single-pass unnormalized softmax
// (scores bounded ~|10|, exp cannot overflow fp32).
// Q tile resident in smem; stream K/V tiles of 64 rows.
// 256 threads; Sc: 8x4/thread over 192 dims; PV: 8x8/thread over 64 dims.
// ---------------------------------------------------------------------------
#define ATTN_SMEM_FLOATS (192*132 + 192*68 + 64*132 + 64*128 + 128)

__global__ __launch_bounds__(256)
void attn_kernel(const float* __restrict__ q, float* __restrict__ out) {
    extern __shared__ float sm[];
    float* Qs = sm;                  // [192][132]  (k-major, padded)
    float* Ks = Qs + 192 * 132;      // [192][68]
    float* Ps = Ks + 192 * 68;       // [64][132]   (n-major, padded)
    float* Vs = Ps + 64 * 132;       // [64][128]
    float* rs = Vs + 64 * 128;       // [128] row sums

    const int h  = blockIdx.y;
    const int t0 = blockIdx.x * 128;
    const int tid = threadIdx.x;
    const int ty = tid >> 4, tx = tid & 15;
    const int m0 = ty * 8;
    const int n0 = tx * 4;   // score cols
    const int v0 = tx * 8;   // value cols

    // Load Q tile transposed: Qs[d][m] = q[t0+m, h, d]
    for (int idx = tid; idx < 128 * 192; idx += 256) {
        int m = idx / 192, d = idx - m * 192;
        Qs[d * 132 + m] = q[(t0 + m) * (HH * DK) + h * DK + d];
    }
    if (tid < 128) rs[tid] = 0.f;

    float O[8][8];
    float rsum[8];
    #pragma unroll
    for (int i = 0; i < 8; i++) {
        rsum[i] = 0.f;
        #pragma unroll
        for (int j = 0; j < 8; j++) O[i][j] = 0.f;
    }
    __syncthreads();

    const float* gK = g_K + h * SS * DK;
    const float4* gV4 = (const float4*)(g_V + h * SS * DV);

    for (int s0 = 0; s0 < SS; s0 += 64) {
        // K tile transposed: Ks[d][n]
        for (int idx = tid; idx < 64 * 192; idx += 256) {
            int n = idx / 192, d = idx - n * 192;
            Ks[d * 68 + n] = gK[(s0 + n) * DK + d];
        }
        // V tile (row-major, contiguous copy)
        {
            const float4* src = gV4 + s0 * (DV / 4);
            float4* dst = (float4*)Vs;
            #pragma unroll
            for (int i = 0; i < 8; i++) dst[tid + i * 256] = src[tid + i * 256];
        }
        __syncthreads();

        // scores: acc[m][n] = sum_k Q[m][k] * K[n][k]
        float acc[8][4];
        #pragma unroll
        for (int i = 0; i < 8; i++)
            #pragma unroll
            for (int j = 0; j < 4; j++) acc[i][j] = 0.f;

        #pragma unroll 4
        for (int k = 0; k < 192; k++) {
            float4 a0 = *(float4*)&Qs[k * 132 + m0];
            float4 a1 = *(float4*)&Qs[k * 132 + m0 + 4];
            float4 b0 = *(float4*)&Ks[k * 68 + n0];
            float am[8] = {a0.x,a0.y,a0.z,a0.w,a1.x,a1.y,a1.z,a1.w};
            float bn[4] = {b0.x,b0.y,b0.z,b0.w};
            #pragma unroll
            for (int i = 0; i < 8; i++)
                #pragma unroll
                for (int j = 0; j < 4; j++) acc[i][j] += am[i] * bn[j];
        }

        // exp + accumulate row sums, write P transposed [n][m]
        #pragma unroll
        for (int j = 0; j < 4; j++) {
            #pragma unroll
            for (int i = 0; i < 8; i++) {
                float p = __expf(acc[i][j] * SCALING);
                rsum[i] += p;
                Ps[(n0 + j) * 132 + m0 + i] = p;
            }
        }
        __syncthreads();

        // O += P * V
        #pragma unroll 2
        for (int n = 0; n < 64; n++) {
            float4 p0 = *(float4*)&Ps[n * 132 + m0];
            float4 p1 = *(float4*)&Ps[n * 132 + m0 + 4];
            float4 w0 = *(float4*)&Vs[n * 128 + v0];
            float4 w1 = *(float4*)&Vs[n * 128 + v0 + 4];
            float pm[8] = {p0.x,p0.y,p0.z,p0.w,p1.x,p1.y,p1.z,p1.w};
            float vn[8] = {w0.x,w0.y,w0.z,w0.w,w1.x,w1.y,w1.z,w1.w};
            #pragma unroll
            for (int i = 0; i < 8; i++)
                #pragma unroll
                for (int j = 0; j < 8; j++) O[i][j] += pm[i] * vn[j];
        }
        __syncthreads();
    }

    // reduce row sums across the 16 tx-threads sharing each row
    #pragma unroll
    for (int i = 0; i < 8; i++) atomicAdd(&rs[m0 + i], rsum[i]);
    __syncthreads();

    #pragma unroll
    for (int i = 0; i < 8; i++) {
        float inv = 1.0f / rs[m0 + i];
        float* dst = out + (t0 + m0 + i) * (HH * DV) + h * DV + v0;
        #pragma unroll
        for (int j = 0; j < 8; j++) dst[j] = O[i][j] * inv;
    }
}

extern "C" void kernel_launch(void* const* d_in, const int* in_sizes, int n_in,
                              void* d_out, int out_size) {
    const float* q    = (const float*)d_in[0];   // (1024, 16, 192)
    const float* kv   = (const float*)d_in[1];   // (8192, 576)
    const float* w_kc = (const float*)d_in[2];   // (16, 128, 512)
    const float* w_vc = (const float*)d_in[3];   // (16, 512, 128)
    float* out = (float*)d_out;                  // (1024, 2048)

    (void)in_sizes; (void)n_in; (void)out_size;

    cudaFuncSetAttribute(attn_kernel, cudaFuncAttributeMaxDynamicSharedMemorySize,
                         ATTN_SMEM_FLOATS * (int)sizeof(float));

    dim3 pgrid(SS / 128, HH);
    proj_kernel<0><<<pgrid, 256>>>(kv, w_kc);
    proj_kernel<1><<<pgrid, 256>>>(kv, w_vc);

    dim3 agrid(TT / 128, HH);
    attn_kernel<<<agrid, 256, ATTN_SMEM_FLOATS * (int)sizeof(float)>>>(q, out);
}

// round 3
// speedup vs baseline: 3.7745x; 3.7745x over previous
#include <cuda_runtime.h>
#include <cuda_bf16.h>
#include <cstdint>

#define TT 1024
#define HH 16
#define SS 8192
#define DK 192      // 128 absorbed + 64 rope
#define DV 128
#define LORA 512
#define KV_W 576
#define SN 32
#define NT (SS / SN)
#define SCALING 0.07216878364870322f  // 1/sqrt(192)

// Split bf16 (hi/lo) absorbed K and V, per head
__device__ __nv_bfloat16 g_Kh[(size_t)HH * SS * DK];
__device__ __nv_bfloat16 g_Kl[(size_t)HH * SS * DK];
__device__ __nv_bfloat16 g_Vh[(size_t)HH * SS * DV];
__device__ __nv_bfloat16 g_Vl[(size_t)HH * SS * DV];

// ===================== helpers =====================
__device__ __forceinline__ uint32_t smem_u32(const void* p) {
    uint32_t a;
    asm("{ .reg .u64 t; cvta.to.shared.u64 t, %1; cvt.u32.u64 %0, t; }" : "=r"(a) : "l"(p));
    return a;
}

__device__ __forceinline__ void ldsm4(uint32_t* r, uint32_t a) {
    asm volatile("ldmatrix.sync.aligned.m8n8.x4.shared.b16 {%0,%1,%2,%3}, [%4];"
        : "=r"(r[0]), "=r"(r[1]), "=r"(r[2]), "=r"(r[3]) : "r"(a));
}
__device__ __forceinline__ void ldsm4t(uint32_t* r, uint32_t a) {
    asm volatile("ldmatrix.sync.aligned.m8n8.x4.trans.shared.b16 {%0,%1,%2,%3}, [%4];"
        : "=r"(r[0]), "=r"(r[1]), "=r"(r[2]), "=r"(r[3]) : "r"(a));
}
__device__ __forceinline__ void mma16816(float* d, const uint32_t* a, const uint32_t* b) {
    asm volatile("mma.sync.aligned.m16n8k16.row.col.f32.bf16.bf16.f32 "
        "{%0,%1,%2,%3}, {%4,%5,%6,%7}, {%8,%9}, {%0,%1,%2,%3};"
        : "+f"(d[0]), "+f"(d[1]), "+f"(d[2]), "+f"(d[3])
        : "r"(a[0]), "r"(a[1]), "r"(a[2]), "r"(a[3]), "r"(b[0]), "r"(b[1]));
}

// split (x,y) into packed bf16x2 hi + residual lo
__device__ __forceinline__ void split2(float x, float y, uint32_t& hi, uint32_t& lo) {
    __nv_bfloat162 h = __floats2bfloat162_rn(x, y);
    float rx = x - __bfloat162float(h.x);
    float ry = y - __bfloat162float(h.y);
    __nv_bfloat162 l = __floats2bfloat162_rn(rx, ry);
    hi = *(uint32_t*)&h;
    lo = *(uint32_t*)&l;
}

__device__ __forceinline__ void cp16(uint32_t dst, const void* src) {
    asm volatile("cp.async.cg.shared.global [%0], [%1], 16;" :: "r"(dst), "l"(src));
}
#define CP_COMMIT() asm volatile("cp.async.commit_group;" ::: "memory")
#define CP_WAIT0()  asm volatile("cp.async.wait_group 0;" ::: "memory")
#define CP_WAIT1()  asm volatile("cp.async.wait_group 1;" ::: "memory")

// ===================== projection GEMMs (mma.sync, compensated bf16) ==========
// MODE 0: g_K[h,s,j] = sum_l kv[s,l] * w_kc[h,j,l]  (j<128) + rope copy
// MODE 1: g_V[h,s,j] = sum_l kv[s,l] * w_vc[h,l,j]
// CTA: 128 s-rows x 128 cols, k-chunks of 32, 256 threads (8 warps x m16).
#define PA_STR 80                  // bytes per A smem row (32 bf16 + pad)
#define PB0_STR 80
#define PB1_STR 272                // 128 bf16 + pad

template<int MODE>
__global__ __launch_bounds__(256)
void proj_mma(const float* __restrict__ kv, const float* __restrict__ w) {
    constexpr int BSZ = (MODE == 0) ? 128 * PB0_STR : 32 * PB1_STR;
    __shared__ __align__(16) char sm[2 * 128 * PA_STR + 2 * BSZ];
    const int AH = 0, AL = 128 * PA_STR, BH = 2 * 128 * PA_STR, BL = BH + BSZ;

    const int h = blockIdx.y, s0 = blockIdx.x * 128;
    const int tid = threadIdx.x, lane = tid & 31, wp = tid >> 5;
    const int grp = lane >> 2, tg = lane & 3;
    const uint32_t sb = smem_u32(sm);

    // loader indices
    const int ar = tid >> 1, ac = (tid & 1) * 16;
    const float* Ap = kv + (size_t)(s0 + ar) * KV_W + ac;
    const float* Bp;
    int br, bc;
    if (MODE == 0) { br = tid >> 1; bc = (tid & 1) * 16; Bp = w + (size_t)h * 128 * 512 + (size_t)br * 512 + bc; }
    else           { br = tid >> 3; bc = (tid & 7) * 16; Bp = w + (size_t)h * 512 * 128 + (size_t)br * 128 + bc; }

    float4 bufA[4], bufB[4];
    #pragma unroll
    for (int i = 0; i < 4; i++) {
        bufA[i] = *(const float4*)(Ap + i * 4);
        bufB[i] = (MODE == 0) ? *(const float4*)(Bp + i * 4)
                              : *(const float4*)(Bp + i * 4);
    }

    float acc[16][4];
    #pragma unroll
    for (int i = 0; i < 16; i++)
        #pragma unroll
        for (int j = 0; j < 4; j++) acc[i][j] = 0.f;

    const int mbase = wp * 16;
    const uint32_t aoff = (uint32_t)((mbase + (lane & 15)) * PA_STR + (lane >> 4) * 16);
    uint32_t boff;
    if (MODE == 0) boff = (uint32_t)((((lane & 7) + ((lane >> 4) & 1) * 8)) * PB0_STR + ((lane >> 3) & 1) * 16);
    else           boff = (uint32_t)((((lane & 7) + ((lane >> 3) & 1) * 8)) * PB1_STR + ((lane >> 4) & 1) * 16);

    for (int kt = 0; kt < LORA; kt += 32) {
        // stage split bf16 into smem
        {
            uint32_t* pAH = (uint32_t*)(sm + AH + ar * PA_STR + ac * 2);
            uint32_t* pAL = (uint32_t*)(sm + AL + ar * PA_STR + ac * 2);
            uint32_t* pBH, *pBL;
            if (MODE == 0) { pBH = (uint32_t*)(sm + BH + br * PB0_STR + bc * 2);
                             pBL = (uint32_t*)(sm + BL + br * PB0_STR + bc * 2); }
            else           { pBH = (uint32_t*)(sm + BH + br * PB1_STR + bc * 2);
                             pBL = (uint32_t*)(sm + BL + br * PB1_STR + bc * 2); }
            #pragma unroll
            for (int i = 0; i < 4; i++) {
                uint32_t h0, l0, h1, l1;
                split2(bufA[i].x, bufA[i].y, h0, l0);
                split2(bufA[i].z, bufA[i].w, h1, l1);
                pAH[2 * i] = h0; pAH[2 * i + 1] = h1;
                pAL[2 * i] = l0; pAL[2 * i + 1] = l1;
                split2(bufB[i].x, bufB[i].y, h0, l0);
                split2(bufB[i].z, bufB[i].w, h1, l1);
                pBH[2 * i] = h0; pBH[2 * i + 1] = h1;
                pBL[2 * i] = l0; pBL[2 * i + 1] = l1;
            }
        }
        __syncthreads();

        // prefetch next chunk
        if (kt + 32 < LORA) {
            #pragma unroll
            for (int i = 0; i < 4; i++) {
                bufA[i] = *(const float4*)(Ap + kt + 32 + i * 4);
                bufB[i] = (MODE == 0) ? *(const float4*)(Bp + kt + 32 + i * 4)
                                      : *(const float4*)(Bp + (size_t)(kt + 32) * 128 + i * 4);
            }
        }

        // mma on the chunk
        #pragma unroll
        for (int ks = 0; ks < 2; ks++) {
            uint32_t ah[4], al[4];
            ldsm4(ah, sb + AH + aoff + ks * 32);
            ldsm4(al, sb + AL + aoff + ks * 32);
            #pragma unroll
            for (int np = 0; np < 8; np++) {
                uint32_t bh[4], bl[4];
                if (MODE == 0) {
                    ldsm4(bh, sb + BH + boff + np * 16 * PB0_STR + ks * 32);
                    ldsm4(bl, sb + BL + boff + np * 16 * PB0_STR + ks * 32);
                } else {
                    ldsm4t(bh, sb + BH + boff + ks * 16 * PB1_STR + np * 32);
                    ldsm4t(bl, sb + BL + boff + ks * 16 * PB1_STR + np * 32);
                }
                mma16816(acc[np * 2],     ah, bh);
                mma16816(acc[np * 2],     ah, bl);
                mma16816(acc[np * 2],     al, bh);
                mma16816(acc[np * 2 + 1], ah, bh + 2);
                mma16816(acc[np * 2 + 1], ah, bl + 2);
                mma16816(acc[np * 2 + 1], al, bh + 2);
            }
        }
        __syncthreads();
    }

    // epilogue: split accumulators, store hi/lo
    const int r0 = s0 + mbase + grp, r1 = r0 + 8;
    #pragma unroll
    for (int nb = 0; nb < 16; nb++) {
        const int col = nb * 8 + tg * 2;
        uint32_t h0, l0, h1, l1;
        split2(acc[nb][0], acc[nb][1], h0, l0);
        split2(acc[nb][2], acc[nb][3], h1, l1);
        if (MODE == 0) {
            size_t o0 = ((size_t)h * SS + r0) * DK + col;
            size_t o1 = ((size_t)h * SS + r1) * DK + col;
            *(uint32_t*)(g_Kh + o0) = h0; *(uint32_t*)(g_Kl + o0) = l0;
            *(uint32_t*)(g_Kh + o1) = h1; *(uint32_t*)(g_Kl + o1) = l1;
        } else {
            size_t o0 = ((size_t)h * SS + r0) * DV + col;
            size_t o1 = ((size_t)h * SS + r1) * DV + col;
            *(uint32_t*)(g_Vh + o0) = h0; *(uint32_t*)(g_Vl + o0) = l0;
            *(uint32_t*)(g_Vh + o1) = h1; *(uint32_t*)(g_Vl + o1) = l1;
        }
    }

    if (MODE == 0) {
        // rope passthrough dims 128..191
        for (int idx = tid; idx < 128 * 64; idx += 256) {
            int m = idx >> 6, r = idx & 63;
            float v = kv[(size_t)(s0 + m) * KV_W + 512 + r];
            __nv_bfloat16 hb = __float2bfloat16(v);
            size_t off = ((size_t)h * SS + s0 + m) * DK + 128 + r;
            g_Kh[off] = hb;
            g_Kl[off] = __float2bfloat16(v - __bfloat162float(hb));
        }
    }
}

// ===================== attention (mma.sync FA2-style) =====================
#define QSTR 400
#define KSTR 400
#define VSTR 272
#define QH_OFF 0
#define QL_OFF (128 * QSTR)                 // 51200
#define STG_OFF (2 * 128 * QSTR)            // 102400
#define KH_O 0
#define KL_O (SN * KSTR)                    // 12800
#define VH_O (2 * SN * KSTR)                // 25600
#define VL_O (2 * SN * KSTR + SN * VSTR)    // 34304
#define STG_SZ (2 * SN * KSTR + 2 * SN * VSTR)  // 43008
#define ATTN_SMEM (STG_OFF + 2 * STG_SZ)    // 188416

__device__ __forceinline__ void load_stage(uint32_t sb, int h, int s0, int stage, int tid) {
    const uint32_t base = sb + STG_OFF + (uint32_t)stage * STG_SZ;
    const char* gkh = (const char*)(g_Kh + ((size_t)h * SS + s0) * DK);
    const char* gkl = (const char*)(g_Kl + ((size_t)h * SS + s0) * DK);
    #pragma unroll
    for (int i = 0; i < 3; i++) {
        int idx = tid + i * 256;
        int r = idx / 24, c = idx - r * 24;
        cp16(base + KH_O + r * KSTR + c * 16, gkh + r * 384 + c * 16);
        cp16(base + KL_O + r * KSTR + c * 16, gkl + r * 384 + c * 16);
    }
    const char* gvh = (const char*)(g_Vh + ((size_t)h * SS + s0) * DV);
    const char* gvl = (const char*)(g_Vl + ((size_t)h * SS + s0) * DV);
    #pragma unroll
    for (int i = 0; i < 2; i++) {
        int idx = tid + i * 256;
        int r = idx >> 4, c = idx & 15;
        cp16(base + VH_O + r * VSTR + c * 16, gvh + r * 256 + c * 16);
        cp16(base + VL_O + r * VSTR + c * 16, gvl + r * 256 + c * 16);
    }
}

__global__ __launch_bounds__(256)
void attn_mma(const float* __restrict__ q, float* __restrict__ out) {
    extern __shared__ __align__(16) char sm[];
    const uint32_t sb = smem_u32(sm);
    const int tid = threadIdx.x, lane = tid & 31, wp = tid >> 5;
    const int grp = lane >> 2, tg = lane & 3;
    const int h = blockIdx.y, t0 = blockIdx.x * 128;

    // Q load + hi/lo split -> smem
    {
        const int r = tid >> 1, half = tid & 1;
        const float* qp = q + (size_t)(t0 + r) * (HH * DK) + (size_t)h * DK + half * 96;
        uint32_t* pH = (uint32_t*)(sm + QH_OFF + r * QSTR + half * 192);
        uint32_t* pL = (uint32_t*)(sm + QL_OFF + r * QSTR + half * 192);
        #pragma unroll
        for (int i = 0; i < 24; i++) {
            float4 v = *(const float4*)(qp + i * 4);
            uint32_t h0, l0, h1, l1;
            split2(v.x, v.y, h0, l0);
            split2(v.z, v.w, h1, l1);
            pH[2 * i] = h0; pH[2 * i + 1] = h1;
            pL[2 * i] = l0; pL[2 * i + 1] = l1;
        }
    }

    load_stage(sb, h, 0, 0, tid); CP_COMMIT();
    load_stage(sb, h, SN, 1, tid); CP_COMMIT();

    float O[16][4];
    #pragma unroll
    for (int i = 0; i < 16; i++)
        #pragma unroll
        for (int j = 0; j < 4; j++) O[i][j] = 0.f;
    float rs0 = 0.f, rs1 = 0.f;

    const uint32_t qa = sb + QH_OFF + (uint32_t)((wp * 16 + (lane & 15)) * QSTR + (lane >> 4) * 16);
    const uint32_t kboff = (uint32_t)((((lane & 7) + ((lane >> 4) & 1) * 8)) * KSTR + ((lane >> 3) & 1) * 16);
    const uint32_t vboff = (uint32_t)((((lane & 7) + ((lane >> 3) & 1) * 8)) * VSTR + ((lane >> 4) & 1) * 16);

    for (int t = 0; t < NT; t++) {
        if (t == NT - 1) { CP_WAIT0(); } else { CP_WAIT1(); }
        __syncthreads();
        const uint32_t stg = sb + STG_OFF + (uint32_t)(t & 1) * STG_SZ;

        // MMA1: scores S[m16 x 32]
        float S[4][4];
        #pragma unroll
        for (int i = 0; i < 4; i++)
            #pragma unroll
            for (int j = 0; j < 4; j++) S[i][j] = 0.f;

        #pragma unroll
        for (int ks = 0; ks < 12; ks++) {
            uint32_t ah[4], al[4];
            ldsm4(ah, qa + ks * 32);
            ldsm4(al, qa + (QL_OFF - QH_OFF) + ks * 32);
            #pragma unroll
            for (int np = 0; np < 2; np++) {
                uint32_t bh[4], bl[4];
                ldsm4(bh, stg + KH_O + kboff + np * 16 * KSTR + ks * 32);
                ldsm4(bl, stg + KL_O + kboff + np * 16 * KSTR + ks * 32);
                mma16816(S[np * 2],     ah, bh);
                mma16816(S[np * 2],     ah, bl);
                mma16816(S[np * 2],     al, bh);
                mma16816(S[np * 2 + 1], ah, bh + 2);
                mma16816(S[np * 2 + 1], ah, bl + 2);
                mma16816(S[np * 2 + 1], al, bh + 2);
            }
        }

        // softmax (unnormalized, single pass) -> P fragments (A layout)
        uint32_t ph[2][4], pl[2][4];
        #pragma unroll
        for (int kk = 0; kk < 2; kk++) {
            #pragma unroll
            for (int sub = 0; sub < 2; sub++) {
                float* c = S[2 * kk + sub];
                float e0 = __expf(c[0] * SCALING);
                float e1 = __expf(c[1] * SCALING);
                float e2 = __expf(c[2] * SCALING);
                float e3 = __expf(c[3] * SCALING);
                rs0 += e0 + e1;
                rs1 += e2 + e3;
                split2(e0, e1, ph[kk][sub * 2],     pl[kk][sub * 2]);
                split2(e2, e3, ph[kk][sub * 2 + 1], pl[kk][sub * 2 + 1]);
            }
        }

        // MMA2: O += P * V
        #pragma unroll
        for (int kk = 0; kk < 2; kk++) {
            #pragma unroll
            for (int np = 0; np < 8; np++) {
                uint32_t vh[4], vl[4];
                ldsm4t(vh, stg + VH_O + vboff + kk * 16 * VSTR + np * 32);
                ldsm4t(vl, stg + VL_O + vboff + kk * 16 * VSTR + np * 32);
                mma16816(O[np * 2],     ph[kk], vh);
                mma16816(O[np * 2],     pl[kk], vh);
                mma16816(O[np * 2],     ph[kk], vl);
                mma16816(O[np * 2 + 1], ph[kk], vh + 2);
                mma16816(O[np * 2 + 1], pl[kk], vh + 2);
                mma16816(O[np * 2 + 1], ph[kk], vl + 2);
            }
        }
        __syncthreads();

        if (t + 2 < NT) {
            load_stage(sb, h, (t + 2) * SN, t & 1, tid);
            CP_COMMIT();
        }
    }

    // reduce row sums across the quad (lanes sharing a row)
    rs0 += __shfl_xor_sync(0xffffffffu, rs0, 1);
    rs0 += __shfl_xor_sync(0xffffffffu, rs0, 2);
    rs1 += __shfl_xor_sync(0xffffffffu, rs1, 1);
    rs1 += __shfl_xor_sync(0xffffffffu, rs1, 2);
    const float i0 = 1.0f / rs0, i1 = 1.0f / rs1;

    const int r0 = t0 + wp * 16 + grp, r1 = r0 + 8;
    #pragma unroll
    for (int nb = 0; nb < 16; nb++) {
        const int col = h * DV + nb * 8 + tg * 2;
        float2 v0 = make_float2(O[nb][0] * i0, O[nb][1] * i0);
        float2 v1 = make_float2(O[nb][2] * i1, O[nb][3] * i1);
        *(float2*)(out + (size_t)r0 * (HH * DV) + col) = v0;
        *(float2*)(out + (size_t)r1 * (HH * DV) + col) = v1;
    }
}

// ===================== launch =====================
extern "C" void kernel_launch(void* const* d_in, const int* in_sizes, int n_in,
                              void* d_out, int out_size) {
    const float* q    = (const float*)d_in[0];   // (1024, 16, 192)
    const float* kv   = (const float*)d_in[1];   // (8192, 576)
    const float* w_kc = (const float*)d_in[2];   // (16, 128, 512)
    const float* w_vc = (const float*)d_in[3];   // (16, 512, 128)
    float* out = (float*)d_out;                  // (1024, 2048)
    (void)in_sizes; (void)n_in; (void)out_size;

    cudaFuncSetAttribute(attn_mma, cudaFuncAttributeMaxDynamicSharedMemorySize, ATTN_SMEM);

    dim3 pgrid(SS / 128, HH);
    proj_mma<0><<<pgrid, 256>>>(kv, w_kc);
    proj_mma<1><<<pgrid, 256>>>(kv, w_vc);

    dim3 agrid(TT / 128, HH);
    attn_mma<<<agrid, 256, ATTN_SMEM>>>(q, out);
}

// round 4
// speedup vs baseline: 7.5340x; 1.9960x over previous
#include <cuda_runtime.h>
#include <cuda_fp16.h>
#include <cstdint>

#define TT 1024
#define HH 16
#define SS 8192
#define DKA 128     // absorbed dims
#define DR 64       // rope dims
#define DV 128
#define LORA 512
#define KV_W 576
#define SN 32
#define NT (SS / SN)
#define SCALING 0.07216878364870322f  // 1/sqrt(192)

// fp16 split inputs + projected operands
__device__ __half g_kvh[(size_t)SS * KV_W];
__device__ __half g_kvl[(size_t)SS * KV_W];
__device__ __half g_wkh[(size_t)HH * DKA * LORA];
__device__ __half g_wvh[(size_t)HH * LORA * DV];
__device__ __half g_wvl[(size_t)HH * LORA * DV];
__device__ __half g_Rh[(size_t)SS * DR];         // shared rope K
__device__ __half g_K[(size_t)HH * SS * DKA];    // absorbed K (hi only)
__device__ __half g_V[(size_t)HH * SS * DV];     // absorbed V (hi only)

// ===================== helpers =====================
__device__ __forceinline__ uint32_t smem_u32(const void* p) {
    uint32_t a;
    asm("{ .reg .u64 t; cvta.to.shared.u64 t, %1; cvt.u32.u64 %0, t; }" : "=r"(a) : "l"(p));
    return a;
}
__device__ __forceinline__ void ldsm4(uint32_t* r, uint32_t a) {
    asm volatile("ldmatrix.sync.aligned.m8n8.x4.shared.b16 {%0,%1,%2,%3}, [%4];"
        : "=r"(r[0]), "=r"(r[1]), "=r"(r[2]), "=r"(r[3]) : "r"(a));
}
__device__ __forceinline__ void ldsm4t(uint32_t* r, uint32_t a) {
    asm volatile("ldmatrix.sync.aligned.m8n8.x4.trans.shared.b16 {%0,%1,%2,%3}, [%4];"
        : "=r"(r[0]), "=r"(r[1]), "=r"(r[2]), "=r"(r[3]) : "r"(a));
}
__device__ __forceinline__ void mma16816h(float* d, const uint32_t* a, const uint32_t* b) {
    asm volatile("mma.sync.aligned.m16n8k16.row.col.f32.f16.f16.f32 "
        "{%0,%1,%2,%3}, {%4,%5,%6,%7}, {%8,%9}, {%0,%1,%2,%3};"
        : "+f"(d[0]), "+f"(d[1]), "+f"(d[2]), "+f"(d[3])
        : "r"(a[0]), "r"(a[1]), "r"(a[2]), "r"(a[3]), "r"(b[0]), "r"(b[1]));
}
__device__ __forceinline__ void split2h(float x, float y, uint32_t& hi, uint32_t& lo) {
    __half2 h = __floats2half2_rn(x, y);
    __half2 l = __floats2half2_rn(x - __low2float(h), y - __high2float(h));
    hi = *(uint32_t*)&h;
    lo = *(uint32_t*)&l;
}
__device__ __forceinline__ void cp16(uint32_t dst, const void* src) {
    asm volatile("cp.async.cg.shared.global [%0], [%1], 16;" :: "r"(dst), "l"(src));
}
#define CP_COMMIT() asm volatile("cp.async.commit_group;" ::: "memory")
#define CP_WAIT0()  asm volatile("cp.async.wait_group 0;" ::: "memory")
#define CP_WAIT1()  asm volatile("cp.async.wait_group 1;" ::: "memory")
#define CP_WAIT2()  asm volatile("cp.async.wait_group 2;" ::: "memory")

// ===================== split kernel (fp32 -> fp16 hi/lo) =====================
#define N1 (SS * KV_W / 4)
#define N2 (HH * DKA * LORA / 4)
#define N3 (HH * LORA * DV / 4)

__global__ __launch_bounds__(256)
void split_kernel(const float* __restrict__ kv, const float* __restrict__ wk,
                  const float* __restrict__ wv) {
    const int i = blockIdx.x * 256 + threadIdx.x;
    if (i < N1) {
        float4 v = ((const float4*)kv)[i];
        uint32_t h0, l0, h1, l1;
        split2h(v.x, v.y, h0, l0);
        split2h(v.z, v.w, h1, l1);
        ((uint32_t*)g_kvh)[2 * i] = h0; ((uint32_t*)g_kvh)[2 * i + 1] = h1;
        ((uint32_t*)g_kvl)[2 * i] = l0; ((uint32_t*)g_kvl)[2 * i + 1] = l1;
        int c = (i * 4) % KV_W;
        if (c >= LORA) {
            int s = (i * 4) / KV_W;
            int o = s * DR + (c - LORA);
            ((uint32_t*)g_Rh)[o / 2]     = h0;
            ((uint32_t*)g_Rh)[o / 2 + 1] = h1;
        }
    } else if (i < N1 + N2) {
        int j = i - N1;
        float4 v = ((const float4*)wk)[j];
        __half2 a = __floats2half2_rn(v.x, v.y);
        __half2 b = __floats2half2_rn(v.z, v.w);
        ((__half2*)g_wkh)[2 * j] = a; ((__half2*)g_wkh)[2 * j + 1] = b;
    } else if (i < N1 + N2 + N3) {
        int j = i - N1 - N2;
        float4 v = ((const float4*)wv)[j];
        uint32_t h0, l0, h1, l1;
        split2h(v.x, v.y, h0, l0);
        split2h(v.z, v.w, h1, l1);
        ((uint32_t*)g_wvh)[2 * j] = h0; ((uint32_t*)g_wvh)[2 * j + 1] = h1;
        ((uint32_t*)g_wvl)[2 * j] = l0; ((uint32_t*)g_wvl)[2 * j + 1] = l1;
    }
}

// ===================== projK: g_K = kv_lora . w_kc^T  (1-combo fp16) ========
#define PSTR 80
#define PK_A 0
#define PK_B (128 * PSTR)           // 10240
#define PK_STAGE (2 * 128 * PSTR)   // 20480

__global__ __launch_bounds__(256)
void projK() {
    __shared__ __align__(16) char sm[2 * PK_STAGE];
    const uint32_t sb = smem_u32(sm);
    const int tid = threadIdx.x, lane = tid & 31, wp = tid >> 5;
    const int grp = lane >> 2, tg = lane & 3;
    const int h = blockIdx.y, s0 = blockIdx.x * 128;

    const __half* Akv = g_kvh + (size_t)s0 * KV_W;
    const __half* Bw  = g_wkh + (size_t)h * DKA * LORA;
    const int lr = tid >> 1;

    #define PK_LOAD(stage, kt) do { \
        uint32_t base_ = sb + (stage) * PK_STAGE; \
        _Pragma("unroll") \
        for (int j_ = 0; j_ < 2; j_++) { \
            int c16_ = (tid & 1) * 2 + j_; \
            cp16(base_ + PK_A + lr * PSTR + c16_ * 16, Akv + (size_t)lr * KV_W + (kt) + c16_ * 8); \
            cp16(base_ + PK_B + lr * PSTR + c16_ * 16, Bw + (size_t)lr * LORA + (kt) + c16_ * 8); \
        } \
    } while (0)

    PK_LOAD(0, 0); CP_COMMIT();

    float acc[16][4];
    #pragma unroll
    for (int i = 0; i < 16; i++)
        #pragma unroll
        for (int j = 0; j < 4; j++) acc[i][j] = 0.f;

    const uint32_t aoff = (uint32_t)((wp * 16 + (lane & 15)) * PSTR + (lane >> 4) * 16);
    const uint32_t boff = (uint32_t)(((lane & 7) + ((lane >> 4) & 1) * 8) * PSTR + ((lane >> 3) & 1) * 16);

    for (int c = 0; c < 16; c++) {
        if (c + 1 < 16) { PK_LOAD((c + 1) & 1, (c + 1) * 32); CP_COMMIT(); CP_WAIT1(); }
        else { CP_WAIT0(); }
        __syncthreads();
        const uint32_t base = sb + (c & 1) * PK_STAGE;
        #pragma unroll
        for (int ks = 0; ks < 2; ks++) {
            uint32_t a[4];
            ldsm4(a, base + PK_A + aoff + ks * 32);
            #pragma unroll
            for (int np = 0; np < 8; np++) {
                uint32_t b[4];
                ldsm4(b, base + PK_B + boff + np * 16 * PSTR + ks * 32);
                mma16816h(acc[np * 2],     a, b);
                mma16816h(acc[np * 2 + 1], a, b + 2);
            }
        }
        __syncthreads();
    }

    const int r0 = s0 + wp * 16 + grp, r1 = r0 + 8;
    #pragma unroll
    for (int nb = 0; nb < 16; nb++) {
        int col = nb * 8 + tg * 2;
        __half2 v0 = __floats2half2_rn(acc[nb][0], acc[nb][1]);
        __half2 v1 = __floats2half2_rn(acc[nb][2], acc[nb][3]);
        *(__half2*)(g_K + ((size_t)h * SS + r0) * DKA + col) = v0;
        *(__half2*)(g_K + ((size_t)h * SS + r1) * DKA + col) = v1;
    }
}

// ===================== projV: g_V = kv_lora . w_vc  (3-combo fp16) ==========
#define PV_AH 0
#define PV_AL (128 * PSTR)                 // 10240
#define PV_BH (2 * 128 * PSTR)             // 20480
#define PV_BSTR 272
#define PV_BL (PV_BH + 32 * PV_BSTR)       // 29184
#define PV_STAGE (PV_BL + 32 * PV_BSTR)    // 37888
#define PV_SMEM (2 * PV_STAGE)             // 75776

__global__ __launch_bounds__(256)
void projV() {
    extern __shared__ __align__(16) char smv[];
    const uint32_t sb = smem_u32(smv);
    const int tid = threadIdx.x, lane = tid & 31, wp = tid >> 5;
    const int grp = lane >> 2, tg = lane & 3;
    const int h = blockIdx.y, s0 = blockIdx.x * 128;

    const __half* Ah = g_kvh + (size_t)s0 * KV_W;
    const __half* Al = g_kvl + (size_t)s0 * KV_W;
    const __half* Bh = g_wvh + (size_t)h * LORA * DV;
    const __half* Bl = g_wvl + (size_t)h * LORA * DV;
    const int lr = tid >> 1;
    const int br = tid >> 3, bcb = (tid & 7) * 2;

    #define PV_LOAD(stage, kt) do { \
        uint32_t base_ = sb + (stage) * PV_STAGE; \
        _Pragma("unroll") \
        for (int j_ = 0; j_ < 2; j_++) { \
            int c16_ = (tid & 1) * 2 + j_; \
            cp16(base_ + PV_AH + lr * PSTR + c16_ * 16, Ah + (size_t)lr * KV_W + (kt) + c16_ * 8); \
            cp16(base_ + PV_AL + lr * PSTR + c16_ * 16, Al + (size_t)lr * KV_W + (kt) + c16_ * 8); \
            int b16_ = bcb + j_; \
            cp16(base_ + PV_BH + br * PV_BSTR + b16_ * 16, Bh + (size_t)((kt) + br) * DV + b16_ * 8); \
            cp16(base_ + PV_BL + br * PV_BSTR + b16_ * 16, Bl + (size_t)((kt) + br) * DV + b16_ * 8); \
        } \
    } while (0)

    PV_LOAD(0, 0); CP_COMMIT();

    float acc[16][4];
    #pragma unroll
    for (int i = 0; i < 16; i++)
        #pragma unroll
        for (int j = 0; j < 4; j++) acc[i][j] = 0.f;

    const uint32_t aoff = (uint32_t)((wp * 16 + (lane & 15)) * PSTR + (lane >> 4) * 16);
    const uint32_t tboff = (uint32_t)(((lane & 7) + ((lane >> 3) & 1) * 8) * PV_BSTR + ((lane >> 4) & 1) * 16);

    for (int c = 0; c < 16; c++) {
        if (c + 1 < 16) { PV_LOAD((c + 1) & 1, (c + 1) * 32); CP_COMMIT(); CP_WAIT1(); }
        else { CP_WAIT0(); }
        __syncthreads();
        const uint32_t base = sb + (c & 1) * PV_STAGE;
        #pragma unroll
        for (int ks = 0; ks < 2; ks++) {
            uint32_t ah[4], al[4];
            ldsm4(ah, base + PV_AH + aoff + ks * 32);
            ldsm4(al, base + PV_AL + aoff + ks * 32);
            #pragma unroll
            for (int np = 0; np < 8; np++) {
                uint32_t bh[4], bl[4];
                ldsm4t(bh, base + PV_BH + tboff + ks * 16 * PV_BSTR + np * 32);
                ldsm4t(bl, base + PV_BL + tboff + ks * 16 * PV_BSTR + np * 32);
                mma16816h(acc[np * 2],     ah, bh);
                mma16816h(acc[np * 2],     ah, bl);
                mma16816h(acc[np * 2],     al, bh);
                mma16816h(acc[np * 2 + 1], ah, bh + 2);
                mma16816h(acc[np * 2 + 1], ah, bl + 2);
                mma16816h(acc[np * 2 + 1], al, bh + 2);
            }
        }
        __syncthreads();
    }

    const int r0 = s0 + wp * 16 + grp, r1 = r0 + 8;
    #pragma unroll
    for (int nb = 0; nb < 16; nb++) {
        int col = nb * 8 + tg * 2;
        __half2 v0 = __floats2half2_rn(acc[nb][0], acc[nb][1]);
        __half2 v1 = __floats2half2_rn(acc[nb][2], acc[nb][3]);
        *(__half2*)(g_V + ((size_t)h * SS + r0) * DV + col) = v0;
        *(__half2*)(g_V + ((size_t)h * SS + r1) * DV + col) = v1;
    }
}

// ===================== attention (fp16 1-combo, Q in registers) =============
#define KSTR2 400
#define VSTR2 272
#define AT_K 0
#define AT_V (SN * KSTR2)             // 12800
#define AT_STG (AT_V + SN * VSTR2)    // 21504
#define AT_Q (3 * AT_STG)             // 64512
#define AT_SMEM (AT_Q + 128 * KSTR2)  // 115712

__device__ __forceinline__ void load_stage(uint32_t sb, int h, int s0, int slot, int tid) {
    const uint32_t base = sb + (uint32_t)slot * AT_STG;
    const __half* gk = g_K + ((size_t)h * SS + s0) * DKA;
    const __half* gr = g_Rh + (size_t)s0 * DR;
    const __half* gv = g_V + ((size_t)h * SS + s0) * DV;
    #pragma unroll
    for (int i = 0; i < 3; i++) {
        int idx = tid + i * 256;
        int r = idx / 24, c = idx - r * 24;
        if (c < 16) cp16(base + AT_K + r * KSTR2 + c * 16, gk + (size_t)r * DKA + c * 8);
        else        cp16(base + AT_K + r * KSTR2 + c * 16, gr + (size_t)r * DR + (c - 16) * 8);
    }
    #pragma unroll
    for (int i = 0; i < 2; i++) {
        int idx = tid + i * 256;
        int r = idx >> 4, c = idx & 15;
        cp16(base + AT_V + r * VSTR2 + c * 16, gv + (size_t)r * DV + c * 8);
    }
}

__global__ __launch_bounds__(256, 1)
void attn_mma(const float* __restrict__ q, float* __restrict__ out) {
    extern __shared__ __align__(16) char sma[];
    const uint32_t sb = smem_u32(sma);
    const int tid = threadIdx.x, lane = tid & 31, wp = tid >> 5;
    const int grp = lane >> 2, tg = lane & 3;
    const int h = blockIdx.y, t0 = blockIdx.x * 128;

    // kick off K/V pipeline first (independent of Q staging)
    load_stage(sb, h, 0, 0, tid); CP_COMMIT();
    load_stage(sb, h, SN, 1, tid); CP_COMMIT();
    load_stage(sb, h, 2 * SN, 2, tid); CP_COMMIT();

    // Q: scale, round fp16, stage, then pull fragments into registers
    {
        const int r = tid >> 1, half = tid & 1;
        const float* qp = q + (size_t)(t0 + r) * (HH * (DKA + DR)) + (size_t)h * (DKA + DR) + half * 96;
        uint32_t* pH = (uint32_t*)(sma + AT_Q + r * KSTR2 + half * 192);
        #pragma unroll
        for (int i = 0; i < 24; i++) {
            float4 v = *(const float4*)(qp + i * 4);
            __half2 a = __floats2half2_rn(v.x * SCALING, v.y * SCALING);
            __half2 b = __floats2half2_rn(v.z * SCALING, v.w * SCALING);
            pH[2 * i]     = *(uint32_t*)&a;
            pH[2 * i + 1] = *(uint32_t*)&b;
        }
    }
    __syncthreads();

    uint32_t qf[12][4];
    {
        const uint32_t qa = sb + AT_Q + (uint32_t)((wp * 16 + (lane & 15)) * KSTR2 + (lane >> 4) * 16);
        #pragma unroll
        for (int ks = 0; ks < 12; ks++) ldsm4(qf[ks], qa + ks * 32);
    }

    float O[16][4];
    #pragma unroll
    for (int i = 0; i < 16; i++)
        #pragma unroll
        for (int j = 0; j < 4; j++) O[i][j] = 0.f;
    float rs0 = 0.f, rs1 = 0.f;

    const uint32_t kboff = (uint32_t)(((lane & 7) + ((lane >> 4) & 1) * 8) * KSTR2 + ((lane >> 3) & 1) * 16);
    const uint32_t vboff = (uint32_t)(((lane & 7) + ((lane >> 3) & 1) * 8) * VSTR2 + ((lane >> 4) & 1) * 16);

    for (int t = 0; t < NT; t++) {
        CP_WAIT2();
        __syncthreads();
        const uint32_t base = sb + (uint32_t)(t % 3) * AT_STG;

        // MMA1: scores
        float S[4][4];
        #pragma unroll
        for (int i = 0; i < 4; i++)
            #pragma unroll
            for (int j = 0; j < 4; j++) S[i][j] = 0.f;

        #pragma unroll
        for (int ks = 0; ks < 12; ks++) {
            #pragma unroll
            for (int np = 0; np < 2; np++) {
                uint32_t b[4];
                ldsm4(b, base + AT_K + kboff + np * 16 * KSTR2 + ks * 32);
                mma16816h(S[np * 2],     qf[ks], b);
                mma16816h(S[np * 2 + 1], qf[ks], b + 2);
            }
        }

        // softmax (unnormalized) -> fp16 A-fragments
        uint32_t ph[2][4];
        #pragma unroll
        for (int kk = 0; kk < 2; kk++) {
            #pragma unroll
            for (int sub = 0; sub < 2; sub++) {
                float* c = S[2 * kk + sub];
                float e0 = __expf(c[0]);
                float e1 = __expf(c[1]);
                float e2 = __expf(c[2]);
                float e3 = __expf(c[3]);
                rs0 += e0 + e1;
                rs1 += e2 + e3;
                __half2 p0 = __floats2half2_rn(e0, e1);
                __half2 p1 = __floats2half2_rn(e2, e3);
                ph[kk][sub * 2]     = *(uint32_t*)&p0;
                ph[kk][sub * 2 + 1] = *(uint32_t*)&p1;
            }
        }

        // MMA2: O += P * V
        #pragma unroll
        for (int kk = 0; kk < 2; kk++) {
            #pragma unroll
            for (int np = 0; np < 8; np++) {
                uint32_t v[4];
                ldsm4t(v, base + AT_V + vboff + kk * 16 * VSTR2 + np * 32);
                mma16816h(O[np * 2],     ph[kk], v);
                mma16816h(O[np * 2 + 1], ph[kk], v + 2);
            }
        }
        __syncthreads();

        if (t + 3 < NT) load_stage(sb, h, (t + 3) * SN, t % 3, tid);
        CP_COMMIT();
    }

    rs0 += __shfl_xor_sync(0xffffffffu, rs0, 1);
    rs0 += __shfl_xor_sync(0xffffffffu, rs0, 2);
    rs1 += __shfl_xor_sync(0xffffffffu, rs1, 1);
    rs1 += __shfl_xor_sync(0xffffffffu, rs1, 2);
    const float i0 = 1.0f / rs0, i1 = 1.0f / rs1;

    const int r0 = t0 + wp * 16 + grp, r1 = r0 + 8;
    #pragma unroll
    for (int nb = 0; nb < 16; nb++) {
        const int col = h * DV + nb * 8 + tg * 2;
        float2 v0 = make_float2(O[nb][0] * i0, O[nb][1] * i0);
        float2 v1 = make_float2(O[nb][2] * i1, O[nb][3] * i1);
        *(float2*)(out + (size_t)r0 * (HH * DV) + col) = v0;
        *(float2*)(out + (size_t)r1 * (HH * DV) + col) = v1;
    }
}

// ===================== launch =====================
extern "C" void kernel_launch(void* const* d_in, const int* in_sizes, int n_in,
                              void* d_out, int out_size) {
    const float* q    = (const float*)d_in[0];   // (1024, 16, 192)
    const float* kv   = (const float*)d_in[1];   // (8192, 576)
    const float* w_kc = (const float*)d_in[2];   // (16, 128, 512)
    const float* w_vc = (const float*)d_in[3];   // (16, 512, 128)
    float* out = (float*)d_out;                  // (1024, 2048)
    (void)in_sizes; (void)n_in; (void)out_size;

    cudaFuncSetAttribute(projV, cudaFuncAttributeMaxDynamicSharedMemorySize, PV_SMEM);
    cudaFuncSetAttribute(attn_mma, cudaFuncAttributeMaxDynamicSharedMemorySize, AT_SMEM);

    split_kernel<<<(N1 + N2 + N3 + 255) / 256, 256>>>(kv, w_kc, w_vc);

    dim3 pgrid(SS / 128, HH);
    projK<<<pgrid, 256>>>();
    projV<<<pgrid, 256, PV_SMEM>>>();

    dim3 agrid(TT / 128, HH);
    attn_mma<<<agrid, 256, AT_SMEM>>>(q, out);
}

// round 5
// speedup vs baseline: 8.3665x; 1.1105x over previous
#include <cuda_runtime.h>
#include <cuda_fp16.h>
#include <cstdint>

#define TT 1024
#define HH 16
#define SS 8192
#define DKA 128     // absorbed dims
#define DR 64       // rope dims
#define DV 128
#define LORA 512
#define KV_W 576
#define SN 32
#define NT (SS / SN)
#define SCALING 0.07216878364870322f  // 1/sqrt(192)

// fp16 split inputs + projected operands
__device__ __half g_kvh[(size_t)SS * KV_W];
__device__ __half g_kvl[(size_t)SS * KV_W];
__device__ __half g_wkh[(size_t)HH * DKA * LORA];
__device__ __half g_wvh[(size_t)HH * LORA * DV];
__device__ __half g_Rh[(size_t)SS * DR];         // shared rope K
__device__ __half g_K[(size_t)HH * SS * DKA];    // absorbed K (hi only)
__device__ __half g_V[(size_t)HH * SS * DV];     // absorbed V (hi only)

// ===================== helpers =====================
__device__ __forceinline__ uint32_t smem_u32(const void* p) {
    uint32_t a;
    asm("{ .reg .u64 t; cvta.to.shared.u64 t, %1; cvt.u32.u64 %0, t; }" : "=r"(a) : "l"(p));
    return a;
}
__device__ __forceinline__ void ldsm4(uint32_t* r, uint32_t a) {
    asm volatile("ldmatrix.sync.aligned.m8n8.x4.shared.b16 {%0,%1,%2,%3}, [%4];"
        : "=r"(r[0]), "=r"(r[1]), "=r"(r[2]), "=r"(r[3]) : "r"(a));
}
__device__ __forceinline__ void ldsm4t(uint32_t* r, uint32_t a) {
    asm volatile("ldmatrix.sync.aligned.m8n8.x4.trans.shared.b16 {%0,%1,%2,%3}, [%4];"
        : "=r"(r[0]), "=r"(r[1]), "=r"(r[2]), "=r"(r[3]) : "r"(a));
}
__device__ __forceinline__ void mma16816h(float* d, const uint32_t* a, const uint32_t* b) {
    asm volatile("mma.sync.aligned.m16n8k16.row.col.f32.f16.f16.f32 "
        "{%0,%1,%2,%3}, {%4,%5,%6,%7}, {%8,%9}, {%0,%1,%2,%3};"
        : "+f"(d[0]), "+f"(d[1]), "+f"(d[2]), "+f"(d[3])
        : "r"(a[0]), "r"(a[1]), "r"(a[2]), "r"(a[3]), "r"(b[0]), "r"(b[1]));
}
__device__ __forceinline__ void split2h(float x, float y, uint32_t& hi, uint32_t& lo) {
    __half2 h = __floats2half2_rn(x, y);
    __half2 l = __floats2half2_rn(x - __low2float(h), y - __high2float(h));
    hi = *(uint32_t*)&h;
    lo = *(uint32_t*)&l;
}
__device__ __forceinline__ void cp16(uint32_t dst, const void* src) {
    asm volatile("cp.async.cg.shared.global [%0], [%1], 16;" :: "r"(dst), "l"(src));
}
#define CP_COMMIT() asm volatile("cp.async.commit_group;" ::: "memory")
#define CP_WAIT0()  asm volatile("cp.async.wait_group 0;" ::: "memory")
#define CP_WAIT1()  asm volatile("cp.async.wait_group 1;" ::: "memory")
#define CP_WAIT2()  asm volatile("cp.async.wait_group 2;" ::: "memory")

// ===================== split kernel (fp32 -> fp16) =====================
#define N1 (SS * KV_W / 4)
#define N2 (HH * DKA * LORA / 4)
#define N3 (HH * LORA * DV / 4)

__global__ __launch_bounds__(256)
void split_kernel(const float* __restrict__ kv, const float* __restrict__ wk,
                  const float* __restrict__ wv) {
    const int i = blockIdx.x * 256 + threadIdx.x;
    if (i < N1) {
        float4 v = ((const float4*)kv)[i];
        uint32_t h0, l0, h1, l1;
        split2h(v.x, v.y, h0, l0);
        split2h(v.z, v.w, h1, l1);
        ((uint32_t*)g_kvh)[2 * i] = h0; ((uint32_t*)g_kvh)[2 * i + 1] = h1;
        ((uint32_t*)g_kvl)[2 * i] = l0; ((uint32_t*)g_kvl)[2 * i + 1] = l1;
        int c = (i * 4) % KV_W;
        if (c >= LORA) {
            int s = (i * 4) / KV_W;
            int o = s * DR + (c - LORA);
            ((uint32_t*)g_Rh)[o / 2]     = h0;
            ((uint32_t*)g_Rh)[o / 2 + 1] = h1;
        }
    } else if (i < N1 + N2) {
        int j = i - N1;
        float4 v = ((const float4*)wk)[j];
        __half2 a = __floats2half2_rn(v.x, v.y);
        __half2 b = __floats2half2_rn(v.z, v.w);
        ((__half2*)g_wkh)[2 * j] = a; ((__half2*)g_wkh)[2 * j + 1] = b;
    } else if (i < N1 + N2 + N3) {
        int j = i - N1 - N2;
        float4 v = ((const float4*)wv)[j];
        __half2 a = __floats2half2_rn(v.x, v.y);
        __half2 b = __floats2half2_rn(v.z, v.w);
        ((__half2*)g_wvh)[2 * j] = a; ((__half2*)g_wvh)[2 * j + 1] = b;
    }
}

// ===================== projK: g_K = kv_lora . w_kc^T  (1-combo fp16) ========
#define PSTR 80
#define PK_A 0
#define PK_B (128 * PSTR)           // 10240
#define PK_STAGE (2 * 128 * PSTR)   // 20480

__global__ __launch_bounds__(256)
void projK() {
    __shared__ __align__(16) char sm[2 * PK_STAGE];
    const uint32_t sb = smem_u32(sm);
    const int tid = threadIdx.x, lane = tid & 31, wp = tid >> 5;
    const int grp = lane >> 2, tg = lane & 3;
    const int h = blockIdx.y, s0 = blockIdx.x * 128;

    const __half* Akv = g_kvh + (size_t)s0 * KV_W;
    const __half* Bw  = g_wkh + (size_t)h * DKA * LORA;
    const int lr = tid >> 1;

    #define PK_LOAD(stage, kt) do { \
        uint32_t base_ = sb + (stage) * PK_STAGE; \
        _Pragma("unroll") \
        for (int j_ = 0; j_ < 2; j_++) { \
            int c16_ = (tid & 1) * 2 + j_; \
            cp16(base_ + PK_A + lr * PSTR + c16_ * 16, Akv + (size_t)lr * KV_W + (kt) + c16_ * 8); \
            cp16(base_ + PK_B + lr * PSTR + c16_ * 16, Bw + (size_t)lr * LORA + (kt) + c16_ * 8); \
        } \
    } while (0)

    PK_LOAD(0, 0); CP_COMMIT();

    float acc[16][4];
    #pragma unroll
    for (int i = 0; i < 16; i++)
        #pragma unroll
        for (int j = 0; j < 4; j++) acc[i][j] = 0.f;

    const uint32_t aoff = (uint32_t)((wp * 16 + (lane & 15)) * PSTR + (lane >> 4) * 16);
    const uint32_t boff = (uint32_t)(((lane & 7) + ((lane >> 4) & 1) * 8) * PSTR + ((lane >> 3) & 1) * 16);

    for (int c = 0; c < 16; c++) {
        if (c + 1 < 16) { PK_LOAD((c + 1) & 1, (c + 1) * 32); CP_COMMIT(); CP_WAIT1(); }
        else { CP_WAIT0(); }
        __syncthreads();
        const uint32_t base = sb + (c & 1) * PK_STAGE;
        #pragma unroll
        for (int ks = 0; ks < 2; ks++) {
            uint32_t a[4];
            ldsm4(a, base + PK_A + aoff + ks * 32);
            #pragma unroll
            for (int np = 0; np < 8; np++) {
                uint32_t b[4];
                ldsm4(b, base + PK_B + boff + np * 16 * PSTR + ks * 32);
                mma16816h(acc[np * 2],     a, b);
                mma16816h(acc[np * 2 + 1], a, b + 2);
            }
        }
        __syncthreads();
    }

    const int r0 = s0 + wp * 16 + grp, r1 = r0 + 8;
    #pragma unroll
    for (int nb = 0; nb < 16; nb++) {
        int col = nb * 8 + tg * 2;
        __half2 v0 = __floats2half2_rn(acc[nb][0], acc[nb][1]);
        __half2 v1 = __floats2half2_rn(acc[nb][2], acc[nb][3]);
        *(__half2*)(g_K + ((size_t)h * SS + r0) * DKA + col) = v0;
        *(__half2*)(g_K + ((size_t)h * SS + r1) * DKA + col) = v1;
    }
}

// ===== projV: g_V = (kv_hi + kv_lo) . w_vc_hi  (exact-A x rounded-B) ========
#define PV_AH 0
#define PV_AL (128 * PSTR)                 // 10240
#define PV_BH (2 * 128 * PSTR)             // 20480
#define PV_BSTR 272
#define PV_STAGE (PV_BH + 32 * PV_BSTR)    // 29184
#define PV_SMEM (2 * PV_STAGE)             // 58368

__global__ __launch_bounds__(256)
void projV() {
    extern __shared__ __align__(16) char smv[];
    const uint32_t sb = smem_u32(smv);
    const int tid = threadIdx.x, lane = tid & 31, wp = tid >> 5;
    const int grp = lane >> 2, tg = lane & 3;
    const int h = blockIdx.y, s0 = blockIdx.x * 128;

    const __half* Ah = g_kvh + (size_t)s0 * KV_W;
    const __half* Al = g_kvl + (size_t)s0 * KV_W;
    const __half* Bh = g_wvh + (size_t)h * LORA * DV;
    const int lr = tid >> 1;
    const int br = tid >> 3, bcb = (tid & 7) * 2;

    #define PV_LOAD(stage, kt) do { \
        uint32_t base_ = sb + (stage) * PV_STAGE; \
        _Pragma("unroll") \
        for (int j_ = 0; j_ < 2; j_++) { \
            int c16_ = (tid & 1) * 2 + j_; \
            cp16(base_ + PV_AH + lr * PSTR + c16_ * 16, Ah + (size_t)lr * KV_W + (kt) + c16_ * 8); \
            cp16(base_ + PV_AL + lr * PSTR + c16_ * 16, Al + (size_t)lr * KV_W + (kt) + c16_ * 8); \
            int b16_ = bcb + j_; \
            cp16(base_ + PV_BH + br * PV_BSTR + b16_ * 16, Bh + (size_t)((kt) + br) * DV + b16_ * 8); \
        } \
    } while (0)

    PV_LOAD(0, 0); CP_COMMIT();

    float acc[16][4];
    #pragma unroll
    for (int i = 0; i < 16; i++)
        #pragma unroll
        for (int j = 0; j < 4; j++) acc[i][j] = 0.f;

    const uint32_t aoff = (uint32_t)((wp * 16 + (lane & 15)) * PSTR + (lane >> 4) * 16);
    const uint32_t tboff = (uint32_t)(((lane & 7) + ((lane >> 3) & 1) * 8) * PV_BSTR + ((lane >> 4) & 1) * 16);

    for (int c = 0; c < 16; c++) {
        if (c + 1 < 16) { PV_LOAD((c + 1) & 1, (c + 1) * 32); CP_COMMIT(); CP_WAIT1(); }
        else { CP_WAIT0(); }
        __syncthreads();
        const uint32_t base = sb + (c & 1) * PV_STAGE;
        #pragma unroll
        for (int ks = 0; ks < 2; ks++) {
            uint32_t ah[4], al[4];
            ldsm4(ah, base + PV_AH + aoff + ks * 32);
            ldsm4(al, base + PV_AL + aoff + ks * 32);
            #pragma unroll
            for (int np = 0; np < 8; np++) {
                uint32_t bh[4];
                ldsm4t(bh, base + PV_BH + tboff + ks * 16 * PV_BSTR + np * 32);
                mma16816h(acc[np * 2],     ah, bh);
                mma16816h(acc[np * 2],     al, bh);
                mma16816h(acc[np * 2 + 1], ah, bh + 2);
                mma16816h(acc[np * 2 + 1], al, bh + 2);
            }
        }
        __syncthreads();
    }

    const int r0 = s0 + wp * 16 + grp, r1 = r0 + 8;
    #pragma unroll
    for (int nb = 0; nb < 16; nb++) {
        int col = nb * 8 + tg * 2;
        __half2 v0 = __floats2half2_rn(acc[nb][0], acc[nb][1]);
        __half2 v1 = __floats2half2_rn(acc[nb][2], acc[nb][3]);
        *(__half2*)(g_V + ((size_t)h * SS + r0) * DV + col) = v0;
        *(__half2*)(g_V + ((size_t)h * SS + r1) * DV + col) = v1;
    }
}

// ====== attention: 64-query CTAs, 128 threads, 2 CTAs/SM =====================
#define QROWS 64
#define KSTR2 400
#define VSTR2 272
#define AT_K 0
#define AT_V (SN * KSTR2)             // 12800
#define AT_STG (AT_V + SN * VSTR2)    // 21504
#define AT_Q (3 * AT_STG)             // 64512
#define AT_SMEM (AT_Q + QROWS * KSTR2)  // 90112

__device__ __forceinline__ void load_stage(uint32_t sb, int h, int s0, int slot, int tid) {
    const uint32_t base = sb + (uint32_t)slot * AT_STG;
    const __half* gk = g_K + ((size_t)h * SS + s0) * DKA;
    const __half* gr = g_Rh + (size_t)s0 * DR;
    const __half* gv = g_V + ((size_t)h * SS + s0) * DV;
    #pragma unroll
    for (int i = 0; i < 6; i++) {
        int idx = tid + i * 128;
        int r = idx / 24, c = idx - r * 24;
        if (c < 16) cp16(base + AT_K + r * KSTR2 + c * 16, gk + (size_t)r * DKA + c * 8);
        else        cp16(base + AT_K + r * KSTR2 + c * 16, gr + (size_t)r * DR + (c - 16) * 8);
    }
    #pragma unroll
    for (int i = 0; i < 4; i++) {
        int idx = tid + i * 128;
        int r = idx >> 4, c = idx & 15;
        cp16(base + AT_V + r * VSTR2 + c * 16, gv + (size_t)r * DV + c * 8);
    }
}

__global__ __launch_bounds__(128, 2)
void attn_mma(const float* __restrict__ q, float* __restrict__ out) {
    extern __shared__ __align__(16) char sma[];
    const uint32_t sb = smem_u32(sma);
    const int tid = threadIdx.x, lane = tid & 31, wp = tid >> 5;
    const int grp = lane >> 2, tg = lane & 3;
    const int h = blockIdx.y, t0 = blockIdx.x * QROWS;

    // kick off K/V pipeline first (independent of Q staging)
    load_stage(sb, h, 0, 0, tid); CP_COMMIT();
    load_stage(sb, h, SN, 1, tid); CP_COMMIT();
    load_stage(sb, h, 2 * SN, 2, tid); CP_COMMIT();

    // Q: scale, round fp16, stage, then pull fragments into registers
    {
        const int r = tid >> 1, half = tid & 1;
        const float* qp = q + (size_t)(t0 + r) * (HH * (DKA + DR)) + (size_t)h * (DKA + DR) + half * 96;
        uint32_t* pH = (uint32_t*)(sma + AT_Q + r * KSTR2 + half * 192);
        #pragma unroll
        for (int i = 0; i < 24; i++) {
            float4 v = *(const float4*)(qp + i * 4);
            __half2 a = __floats2half2_rn(v.x * SCALING, v.y * SCALING);
            __half2 b = __floats2half2_rn(v.z * SCALING, v.w * SCALING);
            pH[2 * i]     = *(uint32_t*)&a;
            pH[2 * i + 1] = *(uint32_t*)&b;
        }
    }
    __syncthreads();

    uint32_t qf[12][4];
    {
        const uint32_t qa = sb + AT_Q + (uint32_t)((wp * 16 + (lane & 15)) * KSTR2 + (lane >> 4) * 16);
        #pragma unroll
        for (int ks = 0; ks < 12; ks++) ldsm4(qf[ks], qa + ks * 32);
    }

    float O[16][4];
    #pragma unroll
    for (int i = 0; i < 16; i++)
        #pragma unroll
        for (int j = 0; j < 4; j++) O[i][j] = 0.f;
    float rs0 = 0.f, rs1 = 0.f;

    const uint32_t kboff = (uint32_t)(((lane & 7) + ((lane >> 4) & 1) * 8) * KSTR2 + ((lane >> 3) & 1) * 16);
    const uint32_t vboff = (uint32_t)(((lane & 7) + ((lane >> 3) & 1) * 8) * VSTR2 + ((lane >> 4) & 1) * 16);

    for (int t = 0; t < NT; t++) {
        CP_WAIT2();
        __syncthreads();
        const uint32_t base = sb + (uint32_t)(t % 3) * AT_STG;

        // MMA1: scores
        float S[4][4];
        #pragma unroll
        for (int i = 0; i < 4; i++)
            #pragma unroll
            for (int j = 0; j < 4; j++) S[i][j] = 0.f;

        #pragma unroll
        for (int ks = 0; ks < 12; ks++) {
            #pragma unroll
            for (int np = 0; np < 2; np++) {
                uint32_t b[4];
                ldsm4(b, base + AT_K + kboff + np * 16 * KSTR2 + ks * 32);
                mma16816h(S[np * 2],     qf[ks], b);
                mma16816h(S[np * 2 + 1], qf[ks], b + 2);
            }
        }

        // softmax (unnormalized) -> fp16 A-fragments
        uint32_t ph[2][4];
        #pragma unroll
        for (int kk = 0; kk < 2; kk++) {
            #pragma unroll
            for (int sub = 0; sub < 2; sub++) {
                float* c = S[2 * kk + sub];
                float e0 = __expf(c[0]);
                float e1 = __expf(c[1]);
                float e2 = __expf(c[2]);
                float e3 = __expf(c[3]);
                rs0 += e0 + e1;
                rs1 += e2 + e3;
                __half2 p0 = __floats2half2_rn(e0, e1);
                __half2 p1 = __floats2half2_rn(e2, e3);
                ph[kk][sub * 2]     = *(uint32_t*)&p0;
                ph[kk][sub * 2 + 1] = *(uint32_t*)&p1;
            }
        }

        // MMA2: O += P * V
        #pragma unroll
        for (int kk = 0; kk < 2; kk++) {
            #pragma unroll
            for (int np = 0; np < 8; np++) {
                uint32_t v[4];
                ldsm4t(v, base + AT_V + vboff + kk * 16 * VSTR2 + np * 32);
                mma16816h(O[np * 2],     ph[kk], v);
                mma16816h(O[np * 2 + 1], ph[kk], v + 2);
            }
        }
        __syncthreads();

        if (t + 3 < NT) load_stage(sb, h, (t + 3) * SN, t % 3, tid);
        CP_COMMIT();
    }

    rs0 += __shfl_xor_sync(0xffffffffu, rs0, 1);
    rs0 += __shfl_xor_sync(0xffffffffu, rs0, 2);
    rs1 += __shfl_xor_sync(0xffffffffu, rs1, 1);
    rs1 += __shfl_xor_sync(0xffffffffu, rs1, 2);
    const float i0 = 1.0f / rs0, i1 = 1.0f / rs1;

    const int r0 = t0 + wp * 16 + grp, r1 = r0 + 8;
    #pragma unroll
    for (int nb = 0; nb < 16; nb++) {
        const int col = h * DV + nb * 8 + tg * 2;
        float2 v0 = make_float2(O[nb][0] * i0, O[nb][1] * i0);
        float2 v1 = make_float2(O[nb][2] * i1, O[nb][3] * i1);
        *(float2*)(out + (size_t)r0 * (HH * DV) + col) = v0;
        *(float2*)(out + (size_t)r1 * (HH * DV) + col) = v1;
    }
}

// ===================== launch =====================
extern "C" void kernel_launch(void* const* d_in, const int* in_sizes, int n_in,
                              void* d_out, int out_size) {
    const float* q    = (const float*)d_in[0];   // (1024, 16, 192)
    const float* kv   = (const float*)d_in[1];   // (8192, 576)
    const float* w_kc = (const float*)d_in[2];   // (16, 128, 512)
    const float* w_vc = (const float*)d_in[3];   // (16, 512, 128)
    float* out = (float*)d_out;                  // (1024, 2048)
    (void)in_sizes; (void)n_in; (void)out_size;

    cudaFuncSetAttribute(projV, cudaFuncAttributeMaxDynamicSharedMemorySize, PV_SMEM);
    cudaFuncSetAttribute(attn_mma, cudaFuncAttributeMaxDynamicSharedMemorySize, AT_SMEM);

    split_kernel<<<(N1 + N2 + N3 + 255) / 256, 256>>>(kv, w_kc, w_vc);

    dim3 pgrid(SS / 128, HH);
    projK<<<pgrid, 256>>>();
    projV<<<pgrid, 256, PV_SMEM>>>();

    dim3 agrid(TT / QROWS, HH);   // (16, 16) = 256 CTAs
    attn_mma<<<agrid, 128, AT_SMEM>>>(q, out);
}

// round 8
// speedup vs baseline: 8.6595x; 1.0350x over previous
#include <cuda_runtime.h>
#include <cuda_fp16.h>
#include <cstdint>

#define TT 1024
#define HH 16
#define SS 8192
#define DKA 128     // absorbed dims
#define DR 64       // rope dims
#define DV 128
#define LORA 512
#define KV_W 576
#define SN 32
#define NT (SS / SN)
#define SCALING 0.07216878364870322f  // 1/sqrt(192)
#define QSCALE 0.1041216338861046f    // SCALING * log2(e)

// fp16 split inputs + projected operands
__device__ __half g_kvh[(size_t)SS * KV_W];
__device__ __half g_kvl[(size_t)SS * KV_W];
__device__ __half g_wkh[(size_t)HH * DKA * LORA];
__device__ __half g_wvh[(size_t)HH * LORA * DV];
__device__ __half g_Rh[(size_t)SS * DR];         // shared rope K
__device__ __half g_K[(size_t)HH * SS * DKA];    // absorbed K (hi only)
__device__ __half g_V[(size_t)HH * SS * DV];     // absorbed V (hi only)

// ===================== helpers =====================
__device__ __forceinline__ uint32_t smem_u32(const void* p) {
    uint32_t a;
    asm("{ .reg .u64 t; cvta.to.shared.u64 t, %1; cvt.u32.u64 %0, t; }" : "=r"(a) : "l"(p));
    return a;
}
__device__ __forceinline__ void ldsm4(uint32_t* r, uint32_t a) {
    asm volatile("ldmatrix.sync.aligned.m8n8.x4.shared.b16 {%0,%1,%2,%3}, [%4];"
        : "=r"(r[0]), "=r"(r[1]), "=r"(r[2]), "=r"(r[3]) : "r"(a));
}
__device__ __forceinline__ void ldsm4t(uint32_t* r, uint32_t a) {
    asm volatile("ldmatrix.sync.aligned.m8n8.x4.trans.shared.b16 {%0,%1,%2,%3}, [%4];"
        : "=r"(r[0]), "=r"(r[1]), "=r"(r[2]), "=r"(r[3]) : "r"(a));
}
__device__ __forceinline__ void mma16816h(float* d, const uint32_t* a, const uint32_t* b) {
    asm volatile("mma.sync.aligned.m16n8k16.row.col.f32.f16.f16.f32 "
        "{%0,%1,%2,%3}, {%4,%5,%6,%7}, {%8,%9}, {%0,%1,%2,%3};"
        : "+f"(d[0]), "+f"(d[1]), "+f"(d[2]), "+f"(d[3])
        : "r"(a[0]), "r"(a[1]), "r"(a[2]), "r"(a[3]), "r"(b[0]), "r"(b[1]));
}
__device__ __forceinline__ float ex2f(float x) {
    float r;
    asm("ex2.approx.f32 %0, %1;" : "=f"(r) : "f"(x));
    return r;
}
__device__ __forceinline__ void split2h(float x, float y, uint32_t& hi, uint32_t& lo) {
    __half2 h = __floats2half2_rn(x, y);
    __half2 l = __floats2half2_rn(x - __low2float(h), y - __high2float(h));
    hi = *(uint32_t*)&h;
    lo = *(uint32_t*)&l;
}
__device__ __forceinline__ void cp16(uint32_t dst, const void* src) {
    asm volatile("cp.async.cg.shared.global [%0], [%1], 16;" :: "r"(dst), "l"(src));
}
#define CP_COMMIT() asm volatile("cp.async.commit_group;" ::: "memory")
#define CP_WAIT0()  asm volatile("cp.async.wait_group 0;" ::: "memory")
#define CP_WAIT1()  asm volatile("cp.async.wait_group 1;" ::: "memory")
#define CP_WAIT2()  asm volatile("cp.async.wait_group 2;" ::: "memory")

// ===================== split kernel (fp32 -> fp16) =====================
#define N1 (SS * KV_W / 4)
#define N2 (HH * DKA * LORA / 4)
#define N3 (HH * LORA * DV / 4)

__global__ __launch_bounds__(256)
void split_kernel(const float* __restrict__ kv, const float* __restrict__ wk,
                  const float* __restrict__ wv) {
    const int i = blockIdx.x * 256 + threadIdx.x;
    if (i < N1) {
        float4 v = ((const float4*)kv)[i];
        uint32_t h0, l0, h1, l1;
        split2h(v.x, v.y, h0, l0);
        split2h(v.z, v.w, h1, l1);
        ((uint32_t*)g_kvh)[2 * i] = h0; ((uint32_t*)g_kvh)[2 * i + 1] = h1;
        ((uint32_t*)g_kvl)[2 * i] = l0; ((uint32_t*)g_kvl)[2 * i + 1] = l1;
        int c = (i * 4) % KV_W;
        if (c >= LORA) {
            int s = (i * 4) / KV_W;
            int o = s * DR + (c - LORA);
            ((uint32_t*)g_Rh)[o / 2]     = h0;
            ((uint32_t*)g_Rh)[o / 2 + 1] = h1;
        }
    } else if (i < N1 + N2) {
        int j = i - N1;
        float4 v = ((const float4*)wk)[j];
        __half2 a = __floats2half2_rn(v.x, v.y);
        __half2 b = __floats2half2_rn(v.z, v.w);
        ((__half2*)g_wkh)[2 * j] = a; ((__half2*)g_wkh)[2 * j + 1] = b;
    } else if (i < N1 + N2 + N3) {
        int j = i - N1 - N2;
        float4 v = ((const float4*)wv)[j];
        __half2 a = __floats2half2_rn(v.x, v.y);
        __half2 b = __floats2half2_rn(v.z, v.w);
        ((__half2*)g_wvh)[2 * j] = a; ((__half2*)g_wvh)[2 * j + 1] = b;
    }
}

// ===================== projK: g_K = kv_lora . w_kc^T  (1-combo fp16) ========
#define PSTR 80
#define PK_A 0
#define PK_B (128 * PSTR)           // 10240
#define PK_STAGE (2 * 128 * PSTR)   // 20480

__global__ __launch_bounds__(256)
void projK() {
    __shared__ __align__(16) char sm[2 * PK_STAGE];
    const uint32_t sb = smem_u32(sm);
    const int tid = threadIdx.x, lane = tid & 31, wp = tid >> 5;
    const int grp = lane >> 2, tg = lane & 3;
    const int h = blockIdx.y, s0 = blockIdx.x * 128;

    const __half* Akv = g_kvh + (size_t)s0 * KV_W;
    const __half* Bw  = g_wkh + (size_t)h * DKA * LORA;
    const int lr = tid >> 1;

    #define PK_LOAD(stage, kt) do { \
        uint32_t base_ = sb + (stage) * PK_STAGE; \
        _Pragma("unroll") \
        for (int j_ = 0; j_ < 2; j_++) { \
            int c16_ = (tid & 1) * 2 + j_; \
            cp16(base_ + PK_A + lr * PSTR + c16_ * 16, Akv + (size_t)lr * KV_W + (kt) + c16_ * 8); \
            cp16(base_ + PK_B + lr * PSTR + c16_ * 16, Bw + (size_t)lr * LORA + (kt) + c16_ * 8); \
        } \
    } while (0)

    PK_LOAD(0, 0); CP_COMMIT();

    float acc[16][4];
    #pragma unroll
    for (int i = 0; i < 16; i++)
        #pragma unroll
        for (int j = 0; j < 4; j++) acc[i][j] = 0.f;

    const uint32_t aoff = (uint32_t)((wp * 16 + (lane & 15)) * PSTR + (lane >> 4) * 16);
    const uint32_t boff = (uint32_t)(((lane & 7) + ((lane >> 4) & 1) * 8) * PSTR + ((lane >> 3) & 1) * 16);

    for (int c = 0; c < 16; c++) {
        if (c + 1 < 16) { PK_LOAD((c + 1) & 1, (c + 1) * 32); CP_COMMIT(); CP_WAIT1(); }
        else { CP_WAIT0(); }
        __syncthreads();
        const uint32_t base = sb + (c & 1) * PK_STAGE;
        #pragma unroll
        for (int ks = 0; ks < 2; ks++) {
            uint32_t a[4];
            ldsm4(a, base + PK_A + aoff + ks * 32);
            #pragma unroll
            for (int np = 0; np < 8; np++) {
                uint32_t b[4];
                ldsm4(b, base + PK_B + boff + np * 16 * PSTR + ks * 32);
                mma16816h(acc[np * 2],     a, b);
                mma16816h(acc[np * 2 + 1], a, b + 2);
            }
        }
        __syncthreads();
    }

    const int r0 = s0 + wp * 16 + grp, r1 = r0 + 8;
    #pragma unroll
    for (int nb = 0; nb < 16; nb++) {
        int col = nb * 8 + tg * 2;
        __half2 v0 = __floats2half2_rn(acc[nb][0], acc[nb][1]);
        __half2 v1 = __floats2half2_rn(acc[nb][2], acc[nb][3]);
        *(__half2*)(g_K + ((size_t)h * SS + r0) * DKA + col) = v0;
        *(__half2*)(g_K + ((size_t)h * SS + r1) * DKA + col) = v1;
    }
}

// ===== projV: g_V = (kv_hi + kv_lo) . w_vc_hi  (exact-A x rounded-B) ========
#define PV_AH 0
#define PV_AL (128 * PSTR)                 // 10240
#define PV_BH (2 * 128 * PSTR)             // 20480
#define PV_BSTR 272
#define PV_STAGE (PV_BH + 32 * PV_BSTR)    // 29184
#define PV_SMEM (2 * PV_STAGE)             // 58368

__global__ __launch_bounds__(256)
void projV() {
    extern __shared__ __align__(16) char smv[];
    const uint32_t sb = smem_u32(smv);
    const int tid = threadIdx.x, lane = tid & 31, wp = tid >> 5;
    const int grp = lane >> 2, tg = lane & 3;
    const int h = blockIdx.y, s0 = blockIdx.x * 128;

    const __half* Ah = g_kvh + (size_t)s0 * KV_W;
    const __half* Al = g_kvl + (size_t)s0 * KV_W;
    const __half* Bh = g_wvh + (size_t)h * LORA * DV;
    const int lr = tid >> 1;
    const int br = tid >> 3, bcb = (tid & 7) * 2;

    #define PV_LOAD(stage, kt) do { \
        uint32_t base_ = sb + (stage) * PV_STAGE; \
        _Pragma("unroll") \
        for (int j_ = 0; j_ < 2; j_++) { \
            int c16_ = (tid & 1) * 2 + j_; \
            cp16(base_ + PV_AH + lr * PSTR + c16_ * 16, Ah + (size_t)lr * KV_W + (kt) + c16_ * 8); \
            cp16(base_ + PV_AL + lr * PSTR + c16_ * 16, Al + (size_t)lr * KV_W + (kt) + c16_ * 8); \
            int b16_ = bcb + j_; \
            cp16(base_ + PV_BH + br * PV_BSTR + b16_ * 16, Bh + (size_t)((kt) + br) * DV + b16_ * 8); \
        } \
    } while (0)

    PV_LOAD(0, 0); CP_COMMIT();

    float acc[16][4];
    #pragma unroll
    for (int i = 0; i < 16; i++)
        #pragma unroll
        for (int j = 0; j < 4; j++) acc[i][j] = 0.f;

    const uint32_t aoff = (uint32_t)((wp * 16 + (lane & 15)) * PSTR + (lane >> 4) * 16);
    const uint32_t tboff = (uint32_t)(((lane & 7) + ((lane >> 3) & 1) * 8) * PV_BSTR + ((lane >> 4) & 1) * 16);

    for (int c = 0; c < 16; c++) {
        if (c + 1 < 16) { PV_LOAD((c + 1) & 1, (c + 1) * 32); CP_COMMIT(); CP_WAIT1(); }
        else { CP_WAIT0(); }
        __syncthreads();
        const uint32_t base = sb + (c & 1) * PV_STAGE;
        #pragma unroll
        for (int ks = 0; ks < 2; ks++) {
            uint32_t ah[4], al[4];
            ldsm4(ah, base + PV_AH + aoff + ks * 32);
            ldsm4(al, base + PV_AL + aoff + ks * 32);
            #pragma unroll
            for (int np = 0; np < 8; np++) {
                uint32_t bh[4];
                ldsm4t(bh, base + PV_BH + tboff + ks * 16 * PV_BSTR + np * 32);
                mma16816h(acc[np * 2],     ah, bh);
                mma16816h(acc[np * 2],     al, bh);
                mma16816h(acc[np * 2 + 1], ah, bh + 2);
                mma16816h(acc[np * 2 + 1], al, bh + 2);
            }
        }
        __syncthreads();
    }

    const int r0 = s0 + wp * 16 + grp, r1 = r0 + 8;
    #pragma unroll
    for (int nb = 0; nb < 16; nb++) {
        int col = nb * 8 + tg * 2;
        __half2 v0 = __floats2half2_rn(acc[nb][0], acc[nb][1]);
        __half2 v1 = __floats2half2_rn(acc[nb][2], acc[nb][3]);
        *(__half2*)(g_V + ((size_t)h * SS + r0) * DV + col) = v0;
        *(__half2*)(g_V + ((size_t)h * SS + r1) * DV + col) = v1;
    }
}

// ====== attention: 64-query CTAs, 4 slots, 1 barrier/tile, fp32 ex2 =========
#define QROWS 64
#define KSTR2 400
#define VSTR2 304                       // 144 cols (128 V + ones + pad)
#define AT_K 0
#define AT_V (SN * KSTR2)               // 12800
#define AT_STG (AT_V + SN * VSTR2)      // 22528
#define AT_Q (2 * AT_STG)               // Q overlay in slots 2-3 region
#define AT_SMEM (4 * AT_STG)            // 90112

__device__ __forceinline__ void load_stage(uint32_t sb, int h, int s0, int slot, int tid) {
    const uint32_t base = sb + (uint32_t)slot * AT_STG;
    const __half* gk = g_K + ((size_t)h * SS + s0) * DKA;
    const __half* gr = g_Rh + (size_t)s0 * DR;
    const __half* gv = g_V + ((size_t)h * SS + s0) * DV;
    #pragma unroll
    for (int i = 0; i < 6; i++) {
        int idx = tid + i * 128;
        int r = idx / 24, c = idx - r * 24;
        if (c < 16) cp16(base + AT_K + r * KSTR2 + c * 16, gk + (size_t)r * DKA + c * 8);
        else        cp16(base + AT_K + r * KSTR2 + c * 16, gr + (size_t)r * DR + (c - 16) * 8);
    }
    #pragma unroll
    for (int i = 0; i < 4; i++) {
        int idx = tid + i * 128;
        int r = idx >> 4, c = idx & 15;
        cp16(base + AT_V + r * VSTR2 + c * 16, gv + (size_t)r * DV + c * 8);
    }
}

__global__ __launch_bounds__(128, 2)
void attn_mma(const float* __restrict__ q, float* __restrict__ out) {
    extern __shared__ __align__(16) char sma[];
    const uint32_t sb = smem_u32(sma);
    const int tid = threadIdx.x, lane = tid & 31, wp = tid >> 5;
    const int grp = lane >> 2, tg = lane & 3;
    const int h = blockIdx.y, t0 = blockIdx.x * QROWS;

    // slots 0,1 first (independent of Q staging)
    load_stage(sb, h, 0, 0, tid); CP_COMMIT();
    load_stage(sb, h, SN, 1, tid); CP_COMMIT();

    // Q: scale by SCALING*log2e, round fp16, stage in slot 2-3 overlay
    {
        const int r = tid >> 1, half = tid & 1;
        const float* qp = q + (size_t)(t0 + r) * (HH * (DKA + DR)) + (size_t)h * (DKA + DR) + half * 96;
        uint32_t* pH = (uint32_t*)(sma + AT_Q + r * KSTR2 + half * 192);
        #pragma unroll
        for (int i = 0; i < 24; i++) {
            float4 v = *(const float4*)(qp + i * 4);
            __half2 a = __floats2half2_rn(v.x * QSCALE, v.y * QSCALE);
            __half2 b = __floats2half2_rn(v.z * QSCALE, v.w * QSCALE);
            pH[2 * i]     = *(uint32_t*)&a;
            pH[2 * i + 1] = *(uint32_t*)&b;
        }
    }
    __syncthreads();

    uint32_t qf[12][4];
    {
        const uint32_t qa = sb + AT_Q + (uint32_t)((wp * 16 + (lane & 15)) * KSTR2 + (lane >> 4) * 16);
        #pragma unroll
        for (int ks = 0; ks < 12; ks++) ldsm4(qf[ks], qa + ks * 32);
    }
    // CRITICAL: all warps must finish reading Q fragments before the
    // ones-column init below overwrites parts of the Q overlay region.
    __syncthreads();

    // ones-column init: all 4 slots, V cols 128..143 (col 128 = 1.0)
    {
        const __half2 one0 = __halves2half2(__float2half(1.f), __float2half(0.f));
        const __half2 zero = __halves2half2(__float2half(0.f), __float2half(0.f));
        #pragma unroll
        for (int i = 0; i < 8; i++) {
            int idx = tid + i * 128;           // 1024 = 4 slots * 32 rows * 8 half2
            int slot = idx >> 8;
            int rem = idx & 255;
            int r = rem >> 3, c2 = rem & 7;
            *(__half2*)(sma + slot * AT_STG + AT_V + r * VSTR2 + 256 + c2 * 4)
                = (c2 == 0) ? one0 : zero;
        }
    }
    __syncthreads();

    load_stage(sb, h, 2 * SN, 2, tid); CP_COMMIT();

    float O[18][4];
    #pragma unroll
    for (int i = 0; i < 18; i++)
        #pragma unroll
        for (int j = 0; j < 4; j++) O[i][j] = 0.f;

    const uint32_t kboff = (uint32_t)(((lane & 7) + ((lane >> 4) & 1) * 8) * KSTR2 + ((lane >> 3) & 1) * 16);
    const uint32_t vboff = (uint32_t)(((lane & 7) + ((lane >> 3) & 1) * 8) * VSTR2 + ((lane >> 4) & 1) * 16);

    for (int t = 0; t < NT; t++) {
        CP_WAIT2();
        __syncthreads();
        const uint32_t base = sb + (uint32_t)(t & 3) * AT_STG;

        // MMA1: scores (log2-domain; QSCALE folded in)
        float S[4][4];
        #pragma unroll
        for (int i = 0; i < 4; i++)
            #pragma unroll
            for (int j = 0; j < 4; j++) S[i][j] = 0.f;

        #pragma unroll
        for (int ks = 0; ks < 12; ks++) {
            #pragma unroll
            for (int np = 0; np < 2; np++) {
                uint32_t b[4];
                ldsm4(b, base + AT_K + kboff + np * 16 * KSTR2 + ks * 32);
                mma16816h(S[np * 2],     qf[ks], b);
                mma16816h(S[np * 2 + 1], qf[ks], b + 2);
            }
        }

        // softmax: p = 2^S in fp32 (MUFU), then pack to fp16 A-fragments
        uint32_t ph[2][4];
        #pragma unroll
        for (int kk = 0; kk < 2; kk++) {
            #pragma unroll
            for (int sub = 0; sub < 2; sub++) {
                float* c = S[2 * kk + sub];
                float e0 = ex2f(c[0]);
                float e1 = ex2f(c[1]);
                float e2 = ex2f(c[2]);
                float e3 = ex2f(c[3]);
                __half2 p0 = __floats2half2_rn(e0, e1);
                __half2 p1 = __floats2half2_rn(e2, e3);
                ph[kk][sub * 2]     = *(uint32_t*)&p0;
                ph[kk][sub * 2 + 1] = *(uint32_t*)&p1;
            }
        }

        // MMA2: O += P * V  (np=8 block carries the ones column -> row sums)
        #pragma unroll
        for (int kk = 0; kk < 2; kk++) {
            #pragma unroll
            for (int np = 0; np < 9; np++) {
                uint32_t v[4];
                ldsm4t(v, base + AT_V + vboff + kk * 16 * VSTR2 + np * 32);
                mma16816h(O[np * 2],     ph[kk], v);
                mma16816h(O[np * 2 + 1], ph[kk], v + 2);
            }
        }
        // no tail barrier: top-of-tile barrier at t proves all warps finished t-1,
        // and slot (t+3)&3 == (t-1)&3 was last read at t-1.
        if (t + 3 < NT) load_stage(sb, h, (t + 3) * SN, (t + 3) & 3, tid);
        CP_COMMIT();
    }

    // row sums came out of the tensor core: block 16, col 128 (tg==0, c[0]/c[2])
    const float r0s = __shfl_sync(0xffffffffu, O[16][0], lane & ~3);
    const float r1s = __shfl_sync(0xffffffffu, O[16][2], lane & ~3);
    const float i0 = 1.0f / r0s, i1 = 1.0f / r1s;

    const int r0 = t0 + wp * 16 + grp, r1 = r0 + 8;
    #pragma unroll
    for (int nb = 0; nb < 16; nb++) {
        const int col = h * DV + nb * 8 + tg * 2;
        float2 v0 = make_float2(O[nb][0] * i0, O[nb][1] * i0);
        float2 v1 = make_float2(O[nb][2] * i1, O[nb][3] * i1);
        *(float2*)(out + (size_t)r0 * (HH * DV) + col) = v0;
        *(float2*)(out + (size_t)r1 * (HH * DV) + col) = v1;
    }
}

// ===================== launch =====================
extern "C" void kernel_launch(void* const* d_in, const int* in_sizes, int n_in,
                              void* d_out, int out_size) {
    const float* q    = (const float*)d_in[0];   // (1024, 16, 192)
    const float* kv   = (const float*)d_in[1];   // (8192, 576)
    const float* w_kc = (const float*)d_in[2];   // (16, 128, 512)
    const float* w_vc = (const float*)d_in[3];   // (16, 512, 128)
    float* out = (float*)d_out;                  // (1024, 2048)
    (void)in_sizes; (void)n_in; (void)out_size;

    cudaFuncSetAttribute(projV, cudaFuncAttributeMaxDynamicSharedMemorySize, PV_SMEM);
    cudaFuncSetAttribute(attn_mma, cudaFuncAttributeMaxDynamicSharedMemorySize, AT_SMEM);

    split_kernel<<<(N1 + N2 + N3 + 255) / 256, 256>>>(kv, w_kc, w_vc);

    dim3 pgrid(SS / 128, HH);
    projK<<<pgrid, 256>>>();
    projV<<<pgrid, 256, PV_SMEM>>>();

    dim3 agrid(TT / QROWS, HH);   // (16, 16) = 256 CTAs
    attn_mma<<<agrid, 128, AT_SMEM>>>(q, out);
}

// round 9
// speedup vs baseline: 9.8444x; 1.1368x over previous
#include <cuda_runtime.h>
#include <cuda_fp16.h>
#include <cstdint>

#define TT 1024
#define HH 16
#define SS 8192
#define DKA 128     // absorbed dims
#define DR 64       // rope dims
#define DV 128
#define LORA 512
#define KV_W 576
#define SN 32
#define NT (SS / SN)
#define QSCALE 0.1041216338861046f    // (1/sqrt(192)) * log2(e)

// fp16 inputs + projected operands
__device__ __half g_kvh[(size_t)SS * KV_W];
__device__ __half g_wkh[(size_t)HH * DKA * LORA];
__device__ __half g_wvh[(size_t)HH * LORA * DV];
__device__ __half g_Rh[(size_t)SS * DR];         // shared rope K
__device__ __half g_K[(size_t)HH * SS * DKA];    // absorbed K
__device__ __half g_V[(size_t)HH * SS * DV];     // absorbed V

// ===================== helpers =====================
__device__ __forceinline__ uint32_t smem_u32(const void* p) {
    uint32_t a;
    asm("{ .reg .u64 t; cvta.to.shared.u64 t, %1; cvt.u32.u64 %0, t; }" : "=r"(a) : "l"(p));
    return a;
}
__device__ __forceinline__ void ldsm4(uint32_t* r, uint32_t a) {
    asm volatile("ldmatrix.sync.aligned.m8n8.x4.shared.b16 {%0,%1,%2,%3}, [%4];"
        : "=r"(r[0]), "=r"(r[1]), "=r"(r[2]), "=r"(r[3]) : "r"(a));
}
__device__ __forceinline__ void ldsm4t(uint32_t* r, uint32_t a) {
    asm volatile("ldmatrix.sync.aligned.m8n8.x4.trans.shared.b16 {%0,%1,%2,%3}, [%4];"
        : "=r"(r[0]), "=r"(r[1]), "=r"(r[2]), "=r"(r[3]) : "r"(a));
}
__device__ __forceinline__ void mma16816h(float* d, const uint32_t* a, const uint32_t* b) {
    asm volatile("mma.sync.aligned.m16n8k16.row.col.f32.f16.f16.f32 "
        "{%0,%1,%2,%3}, {%4,%5,%6,%7}, {%8,%9}, {%0,%1,%2,%3};"
        : "+f"(d[0]), "+f"(d[1]), "+f"(d[2]), "+f"(d[3])
        : "r"(a[0]), "r"(a[1]), "r"(a[2]), "r"(a[3]), "r"(b[0]), "r"(b[1]));
}
__device__ __forceinline__ float ex2f(float x) {
    float r;
    asm("ex2.approx.f32 %0, %1;" : "=f"(r) : "f"(x));
    return r;
}
__device__ __forceinline__ void cp16(uint32_t dst, const void* src) {
    asm volatile("cp.async.cg.shared.global [%0], [%1], 16;" :: "r"(dst), "l"(src));
}
#define CP_COMMIT() asm volatile("cp.async.commit_group;" ::: "memory")
#define CP_WAIT0()  asm volatile("cp.async.wait_group 0;" ::: "memory")
#define CP_WAIT1()  asm volatile("cp.async.wait_group 1;" ::: "memory")

// ===================== split kernel (fp32 -> fp16) =====================
#define N1 (SS * KV_W / 4)
#define N2 (HH * DKA * LORA / 4)
#define N3 (HH * LORA * DV / 4)

__global__ __launch_bounds__(256)
void split_kernel(const float* __restrict__ kv, const float* __restrict__ wk,
                  const float* __restrict__ wv) {
    const int i = blockIdx.x * 256 + threadIdx.x;
    if (i < N1) {
        float4 v = ((const float4*)kv)[i];
        __half2 a = __floats2half2_rn(v.x, v.y);
        __half2 b = __floats2half2_rn(v.z, v.w);
        ((__half2*)g_kvh)[2 * i] = a; ((__half2*)g_kvh)[2 * i + 1] = b;
        int c = (i * 4) % KV_W;
        if (c >= LORA) {
            int s = (i * 4) / KV_W;
            int o = s * DR + (c - LORA);
            ((__half2*)g_Rh)[o / 2]     = a;
            ((__half2*)g_Rh)[o / 2 + 1] = b;
        }
    } else if (i < N1 + N2) {
        int j = i - N1;
        float4 v = ((const float4*)wk)[j];
        __half2 a = __floats2half2_rn(v.x, v.y);
        __half2 b = __floats2half2_rn(v.z, v.w);
        ((__half2*)g_wkh)[2 * j] = a; ((__half2*)g_wkh)[2 * j + 1] = b;
    } else if (i < N1 + N2 + N3) {
        int j = i - N1 - N2;
        float4 v = ((const float4*)wv)[j];
        __half2 a = __floats2half2_rn(v.x, v.y);
        __half2 b = __floats2half2_rn(v.z, v.w);
        ((__half2*)g_wvh)[2 * j] = a; ((__half2*)g_wvh)[2 * j + 1] = b;
    }
}

// ===================== projK: g_K = kv_lora . w_kc^T  (1-combo fp16) ========
#define PSTR 80
#define PK_A 0
#define PK_B (128 * PSTR)           // 10240
#define PK_STAGE (2 * 128 * PSTR)   // 20480

__global__ __launch_bounds__(256)
void projK() {
    __shared__ __align__(16) char sm[2 * PK_STAGE];
    const uint32_t sb = smem_u32(sm);
    const int tid = threadIdx.x, lane = tid & 31, wp = tid >> 5;
    const int grp = lane >> 2, tg = lane & 3;
    const int h = blockIdx.y, s0 = blockIdx.x * 128;

    const __half* Akv = g_kvh + (size_t)s0 * KV_W;
    const __half* Bw  = g_wkh + (size_t)h * DKA * LORA;
    const int lr = tid >> 1;

    #define PK_LOAD(stage, kt) do { \
        uint32_t base_ = sb + (stage) * PK_STAGE; \
        _Pragma("unroll") \
        for (int j_ = 0; j_ < 2; j_++) { \
            int c16_ = (tid & 1) * 2 + j_; \
            cp16(base_ + PK_A + lr * PSTR + c16_ * 16, Akv + (size_t)lr * KV_W + (kt) + c16_ * 8); \
            cp16(base_ + PK_B + lr * PSTR + c16_ * 16, Bw + (size_t)lr * LORA + (kt) + c16_ * 8); \
        } \
    } while (0)

    PK_LOAD(0, 0); CP_COMMIT();

    float acc[16][4];
    #pragma unroll
    for (int i = 0; i < 16; i++)
        #pragma unroll
        for (int j = 0; j < 4; j++) acc[i][j] = 0.f;

    const uint32_t aoff = (uint32_t)((wp * 16 + (lane & 15)) * PSTR + (lane >> 4) * 16);
    const uint32_t boff = (uint32_t)(((lane & 7) + ((lane >> 4) & 1) * 8) * PSTR + ((lane >> 3) & 1) * 16);

    for (int c = 0; c < 16; c++) {
        if (c + 1 < 16) { PK_LOAD((c + 1) & 1, (c + 1) * 32); CP_COMMIT(); CP_WAIT1(); }
        else { CP_WAIT0(); }
        __syncthreads();
        const uint32_t base = sb + (c & 1) * PK_STAGE;
        #pragma unroll
        for (int ks = 0; ks < 2; ks++) {
            uint32_t a[4];
            ldsm4(a, base + PK_A + aoff + ks * 32);
            #pragma unroll
            for (int np = 0; np < 8; np++) {
                uint32_t b[4];
                ldsm4(b, base + PK_B + boff + np * 16 * PSTR + ks * 32);
                mma16816h(acc[np * 2],     a, b);
                mma16816h(acc[np * 2 + 1], a, b + 2);
            }
        }
        __syncthreads();
    }

    const int r0 = s0 + wp * 16 + grp, r1 = r0 + 8;
    #pragma unroll
    for (int nb = 0; nb < 16; nb++) {
        int col = nb * 8 + tg * 2;
        __half2 v0 = __floats2half2_rn(acc[nb][0], acc[nb][1]);
        __half2 v1 = __floats2half2_rn(acc[nb][2], acc[nb][3]);
        *(__half2*)(g_K + ((size_t)h * SS + r0) * DKA + col) = v0;
        *(__half2*)(g_K + ((size_t)h * SS + r1) * DKA + col) = v1;
    }
}

// ===== projV: g_V = kv_hi . w_vc_hi  (1-combo fp16) =========================
#define PV_AH 0
#define PV_BH (128 * PSTR)                 // 10240
#define PV_BSTR 272
#define PV_STAGE (PV_BH + 32 * PV_BSTR)    // 18944
#define PV_SMEM (2 * PV_STAGE)             // 37888

__global__ __launch_bounds__(256)
void projV() {
    extern __shared__ __align__(16) char smv[];
    const uint32_t sb = smem_u32(smv);
    const int tid = threadIdx.x, lane = tid & 31, wp = tid >> 5;
    const int grp = lane >> 2, tg = lane & 3;
    const int h = blockIdx.y, s0 = blockIdx.x * 128;

    const __half* Ah = g_kvh + (size_t)s0 * KV_W;
    const __half* Bh = g_wvh + (size_t)h * LORA * DV;
    const int lr = tid >> 1;
    const int br = tid >> 3, bcb = (tid & 7) * 2;

    #define PV_LOAD(stage, kt) do { \
        uint32_t base_ = sb + (stage) * PV_STAGE; \
        _Pragma("unroll") \
        for (int j_ = 0; j_ < 2; j_++) { \
            int c16_ = (tid & 1) * 2 + j_; \
            cp16(base_ + PV_AH + lr * PSTR + c16_ * 16, Ah + (size_t)lr * KV_W + (kt) + c16_ * 8); \
            int b16_ = bcb + j_; \
            cp16(base_ + PV_BH + br * PV_BSTR + b16_ * 16, Bh + (size_t)((kt) + br) * DV + b16_ * 8); \
        } \
    } while (0)

    PV_LOAD(0, 0); CP_COMMIT();

    float acc[16][4];
    #pragma unroll
    for (int i = 0; i < 16; i++)
        #pragma unroll
        for (int j = 0; j < 4; j++) acc[i][j] = 0.f;

    const uint32_t aoff = (uint32_t)((wp * 16 + (lane & 15)) * PSTR + (lane >> 4) * 16);
    const uint32_t tboff = (uint32_t)(((lane & 7) + ((lane >> 3) & 1) * 8) * PV_BSTR + ((lane >> 4) & 1) * 16);

    for (int c = 0; c < 16; c++) {
        if (c + 1 < 16) { PV_LOAD((c + 1) & 1, (c + 1) * 32); CP_COMMIT(); CP_WAIT1(); }
        else { CP_WAIT0(); }
        __syncthreads();
        const uint32_t base = sb + (c & 1) * PV_STAGE;
        #pragma unroll
        for (int ks = 0; ks < 2; ks++) {
            uint32_t ah[4];
            ldsm4(ah, base + PV_AH + aoff + ks * 32);
            #pragma unroll
            for (int np = 0; np < 8; np++) {
                uint32_t bh[4];
                ldsm4t(bh, base + PV_BH + tboff + ks * 16 * PV_BSTR + np * 32);
                mma16816h(acc[np * 2],     ah, bh);
                mma16816h(acc[np * 2 + 1], ah, bh + 2);
            }
        }
        __syncthreads();
    }

    const int r0 = s0 + wp * 16 + grp, r1 = r0 + 8;
    #pragma unroll
    for (int nb = 0; nb < 16; nb++) {
        int col = nb * 8 + tg * 2;
        __half2 v0 = __floats2half2_rn(acc[nb][0], acc[nb][1]);
        __half2 v1 = __floats2half2_rn(acc[nb][2], acc[nb][3]);
        *(__half2*)(g_V + ((size_t)h * SS + r0) * DV + col) = v0;
        *(__half2*)(g_V + ((size_t)h * SS + r1) * DV + col) = v1;
    }
}

// ====== attention: 64q CTAs, 4 slots, barrier per 2-tile pair, fp32 ex2 =====
#define QROWS 64
#define KSTR2 400
#define VSTR2 304                       // 144 cols (128 V + ones + pad)
#define AT_K 0
#define AT_V (SN * KSTR2)               // 12800
#define AT_STG (AT_V + SN * VSTR2)      // 22528
#define AT_Q (2 * AT_STG)               // Q overlay in slots 2-3 region
#define AT_SMEM (4 * AT_STG)            // 90112

__device__ __forceinline__ void load_stage(uint32_t sb, int h, int s0, int slot, int tid) {
    const uint32_t base = sb + (uint32_t)slot * AT_STG;
    const __half* gk = g_K + ((size_t)h * SS + s0) * DKA;
    const __half* gr = g_Rh + (size_t)s0 * DR;
    const __half* gv = g_V + ((size_t)h * SS + s0) * DV;
    #pragma unroll
    for (int i = 0; i < 6; i++) {
        int idx = tid + i * 128;
        int r = idx / 24, c = idx - r * 24;
        if (c < 16) cp16(base + AT_K + r * KSTR2 + c * 16, gk + (size_t)r * DKA + c * 8);
        else        cp16(base + AT_K + r * KSTR2 + c * 16, gr + (size_t)r * DR + (c - 16) * 8);
    }
    #pragma unroll
    for (int i = 0; i < 4; i++) {
        int idx = tid + i * 128;
        int r = idx >> 4, c = idx & 15;
        cp16(base + AT_V + r * VSTR2 + c * 16, gv + (size_t)r * DV + c * 8);
    }
}

__global__ __launch_bounds__(128, 2)
void attn_mma(const float* __restrict__ q, float* __restrict__ out) {
    extern __shared__ __align__(16) char sma[];
    const uint32_t sb = smem_u32(sma);
    const int tid = threadIdx.x, lane = tid & 31, wp = tid >> 5;
    const int grp = lane >> 2, tg = lane & 3;
    const int h = blockIdx.y, t0 = blockIdx.x * QROWS;

    // pair 0 loads (slots 0,1) as one group
    load_stage(sb, h, 0, 0, tid);
    load_stage(sb, h, SN, 1, tid);
    CP_COMMIT();

    // Q: scale by QSCALE, round fp16, stage in slots 2-3 overlay region
    {
        const int r = tid >> 1, half = tid & 1;
        const float* qp = q + (size_t)(t0 + r) * (HH * (DKA + DR)) + (size_t)h * (DKA + DR) + half * 96;
        uint32_t* pH = (uint32_t*)(sma + AT_Q + r * KSTR2 + half * 192);
        #pragma unroll
        for (int i = 0; i < 24; i++) {
            float4 v = *(const float4*)(qp + i * 4);
            __half2 a = __floats2half2_rn(v.x * QSCALE, v.y * QSCALE);
            __half2 b = __floats2half2_rn(v.z * QSCALE, v.w * QSCALE);
            pH[2 * i]     = *(uint32_t*)&a;
            pH[2 * i + 1] = *(uint32_t*)&b;
        }
    }
    __syncthreads();

    uint32_t qf[12][4];
    {
        const uint32_t qa = sb + AT_Q + (uint32_t)((wp * 16 + (lane & 15)) * KSTR2 + (lane >> 4) * 16);
        #pragma unroll
        for (int ks = 0; ks < 12; ks++) ldsm4(qf[ks], qa + ks * 32);
    }
    // all warps must finish reading Q fragments before the ones-init below
    // overwrites parts of the Q overlay region.
    __syncthreads();

    // ones-column init: all 4 slots, V cols 128..143 (col 128 = 1.0).
    // Disjoint bytes from cp.async V writes (cols 0..127); first reads happen
    // after the pair-0 top barrier, which orders these stores.
    {
        const __half2 one0 = __halves2half2(__float2half(1.f), __float2half(0.f));
        const __half2 zero = __halves2half2(__float2half(0.f), __float2half(0.f));
        #pragma unroll
        for (int i = 0; i < 8; i++) {
            int idx = tid + i * 128;           // 1024 = 4 slots * 32 rows * 8 half2
            int slot = idx >> 8;
            int rem = idx & 255;
            int r = rem >> 3, c2 = rem & 7;
            *(__half2*)(sma + slot * AT_STG + AT_V + r * VSTR2 + 256 + c2 * 4)
                = (c2 == 0) ? one0 : zero;
        }
    }

    float O[18][4];
    #pragma unroll
    for (int i = 0; i < 18; i++)
        #pragma unroll
        for (int j = 0; j < 4; j++) O[i][j] = 0.f;

    const uint32_t kboff = (uint32_t)(((lane & 7) + ((lane >> 4) & 1) * 8) * KSTR2 + ((lane >> 3) & 1) * 16);
    const uint32_t vboff = (uint32_t)(((lane & 7) + ((lane >> 3) & 1) * 8) * VSTR2 + ((lane >> 4) & 1) * 16);

    #define DO_MMA1(Sv, base_) do { \
        _Pragma("unroll") \
        for (int ks = 0; ks < 12; ks++) { \
            _Pragma("unroll") \
            for (int np = 0; np < 2; np++) { \
                uint32_t b[4]; \
                ldsm4(b, (base_) + AT_K + kboff + np * 16 * KSTR2 + ks * 32); \
                mma16816h(Sv[np * 2],     qf[ks], b); \
                mma16816h(Sv[np * 2 + 1], qf[ks], b + 2); \
            } \
        } \
    } while (0)

    #define DO_EXP(Sv, phv) do { \
        _Pragma("unroll") \
        for (int kk = 0; kk < 2; kk++) { \
            _Pragma("unroll") \
            for (int sub = 0; sub < 2; sub++) { \
                float* c = Sv[2 * kk + sub]; \
                float e0 = ex2f(c[0]); \
                float e1 = ex2f(c[1]); \
                float e2 = ex2f(c[2]); \
                float e3 = ex2f(c[3]); \
                __half2 p0 = __floats2half2_rn(e0, e1); \
                __half2 p1 = __floats2half2_rn(e2, e3); \
                phv[kk][sub * 2]     = *(uint32_t*)&p0; \
                phv[kk][sub * 2 + 1] = *(uint32_t*)&p1; \
            } \
        } \
    } while (0)

    #define DO_MMA2(phv, base_) do { \
        _Pragma("unroll") \
        for (int kk = 0; kk < 2; kk++) { \
            _Pragma("unroll") \
            for (int np = 0; np < 9; np++) { \
                uint32_t v[4]; \
                ldsm4t(v, (base_) + AT_V + vboff + kk * 16 * VSTR2 + np * 32); \
                mma16816h(O[np * 2],     phv[kk], v); \
                mma16816h(O[np * 2 + 1], phv[kk], v + 2); \
            } \
        } \
    } while (0)

    for (int p = 0; p < NT / 2; p++) {
        CP_WAIT0();
        __syncthreads();
        // prefetch next pair into the OTHER two slots (last read at pair p-1,
        // covered by the barrier above)
        if (p + 1 < NT / 2) {
            load_stage(sb, h, (2 * p + 2) * SN, (2 * p + 2) & 3, tid);
            load_stage(sb, h, (2 * p + 3) * SN, (2 * p + 3) & 3, tid);
            CP_COMMIT();
        }

        const uint32_t baseA = sb + (uint32_t)((2 * p) & 3) * AT_STG;
        const uint32_t baseB = sb + (uint32_t)((2 * p + 1) & 3) * AT_STG;

        float S0[4][4], S1[4][4];
        #pragma unroll
        for (int i = 0; i < 4; i++)
            #pragma unroll
            for (int j = 0; j < 4; j++) { S0[i][j] = 0.f; S1[i][j] = 0.f; }

        uint32_t ph0[2][4], ph1[2][4];
        DO_MMA1(S0, baseA);
        DO_EXP(S0, ph0);
        DO_MMA1(S1, baseB);        // independent of tile A's exp/MMA2 chain
        DO_MMA2(ph0, baseA);
        DO_EXP(S1, ph1);
        DO_MMA2(ph1, baseB);
    }

    // row sums from the tensor core ones-column: block 16, col 128
    const float r0s = __shfl_sync(0xffffffffu, O[16][0], lane & ~3);
    const float r1s = __shfl_sync(0xffffffffu, O[16][2], lane & ~3);
    const float i0 = 1.0f / r0s, i1 = 1.0f / r1s;

    const int r0 = t0 + wp * 16 + grp, r1 = r0 + 8;
    #pragma unroll
    for (int nb = 0; nb < 16; nb++) {
        const int col = h * DV + nb * 8 + tg * 2;
        float2 v0 = make_float2(O[nb][0] * i0, O[nb][1] * i0);
        float2 v1 = make_float2(O[nb][2] * i1, O[nb][3] * i1);
        *(float2*)(out + (size_t)r0 * (HH * DV) + col) = v0;
        *(float2*)(out + (size_t)r1 * (HH * DV) + col) = v1;
    }
}

// ===================== launch =====================
extern "C" void kernel_launch(void* const* d_in, const int* in_sizes, int n_in,
                              void* d_out, int out_size) {
    const float* q    = (const float*)d_in[0];   // (1024, 16, 192)
    const float* kv   = (const float*)d_in[1];   // (8192, 576)
    const float* w_kc = (const float*)d_in[2];   // (16, 128, 512)
    const float* w_vc = (const float*)d_in[3];   // (16, 512, 128)
    float* out = (float*)d_out;                  // (1024, 2048)
    (void)in_sizes; (void)n_in; (void)out_size;

    cudaFuncSetAttribute(projV, cudaFuncAttributeMaxDynamicSharedMemorySize, PV_SMEM);
    cudaFuncSetAttribute(attn_mma, cudaFuncAttributeMaxDynamicSharedMemorySize, AT_SMEM);

    split_kernel<<<(N1 + N2 + N3 + 255) / 256, 256>>>(kv, w_kc, w_vc);

    dim3 pgrid(SS / 128, HH);
    projK<<<pgrid, 256>>>();
    projV<<<pgrid, 256, PV_SMEM>>>();

    dim3 agrid(TT / QROWS, HH);   // (16, 16) = 256 CTAs
    attn_mma<<<agrid, 128, AT_SMEM>>>(q, out);
}

// round 10
// speedup vs baseline: 10.1927x; 1.0354x over previous
#include <cuda_runtime.h>
#include <cuda_fp16.h>
#include <cstdint>

#define TT 1024
#define HH 16
#define SS 8192
#define DKA 128     // absorbed dims
#define DR 64       // rope dims
#define DV 128
#define LORA 512
#define KV_W 576
#define SN 32
#define NT (SS / SN)
#define QSCALE 0.1041216338861046f    // (1/sqrt(192)) * log2(e)

// fp16 inputs + projected operands
__device__ __half g_kvh[(size_t)SS * KV_W];
__device__ __half g_wkh[(size_t)HH * DKA * LORA];
__device__ __half g_wvh[(size_t)HH * LORA * DV];
__device__ __half g_Rh[(size_t)SS * DR];         // shared rope K
__device__ __half g_K[(size_t)HH * SS * DKA];    // absorbed K
__device__ __half g_V[(size_t)HH * SS * DV];     // absorbed V

// ===================== helpers =====================
__device__ __forceinline__ uint32_t smem_u32(const void* p) {
    uint32_t a;
    asm("{ .reg .u64 t; cvta.to.shared.u64 t, %1; cvt.u32.u64 %0, t; }" : "=r"(a) : "l"(p));
    return a;
}
__device__ __forceinline__ void ldsm4(uint32_t* r, uint32_t a) {
    asm volatile("ldmatrix.sync.aligned.m8n8.x4.shared.b16 {%0,%1,%2,%3}, [%4];"
        : "=r"(r[0]), "=r"(r[1]), "=r"(r[2]), "=r"(r[3]) : "r"(a));
}
__device__ __forceinline__ void ldsm4t(uint32_t* r, uint32_t a) {
    asm volatile("ldmatrix.sync.aligned.m8n8.x4.trans.shared.b16 {%0,%1,%2,%3}, [%4];"
        : "=r"(r[0]), "=r"(r[1]), "=r"(r[2]), "=r"(r[3]) : "r"(a));
}
__device__ __forceinline__ void mma16816h(float* d, const uint32_t* a, const uint32_t* b) {
    asm volatile("mma.sync.aligned.m16n8k16.row.col.f32.f16.f16.f32 "
        "{%0,%1,%2,%3}, {%4,%5,%6,%7}, {%8,%9}, {%0,%1,%2,%3};"
        : "+f"(d[0]), "+f"(d[1]), "+f"(d[2]), "+f"(d[3])
        : "r"(a[0]), "r"(a[1]), "r"(a[2]), "r"(a[3]), "r"(b[0]), "r"(b[1]));
}
__device__ __forceinline__ float ex2f(float x) {
    float r;
    asm("ex2.approx.f32 %0, %1;" : "=f"(r) : "f"(x));
    return r;
}
__device__ __forceinline__ void cp16(uint32_t dst, const void* src) {
    asm volatile("cp.async.cg.shared.global [%0], [%1], 16;" :: "r"(dst), "l"(src));
}
#define CP_COMMIT() asm volatile("cp.async.commit_group;" ::: "memory")
#define CP_WAIT0()  asm volatile("cp.async.wait_group 0;" ::: "memory")
#define CP_WAIT1()  asm volatile("cp.async.wait_group 1;" ::: "memory")
#define CP_WAIT2()  asm volatile("cp.async.wait_group 2;" ::: "memory")

// ===================== split kernel (fp32 -> fp16) =====================
#define N1 (SS * KV_W / 4)
#define N2 (HH * DKA * LORA / 4)
#define N3 (HH * LORA * DV / 4)

__global__ __launch_bounds__(256)
void split_kernel(const float* __restrict__ kv, const float* __restrict__ wk,
                  const float* __restrict__ wv) {
    const int i = blockIdx.x * 256 + threadIdx.x;
    if (i < N1) {
        float4 v = ((const float4*)kv)[i];
        __half2 a = __floats2half2_rn(v.x, v.y);
        __half2 b = __floats2half2_rn(v.z, v.w);
        ((__half2*)g_kvh)[2 * i] = a; ((__half2*)g_kvh)[2 * i + 1] = b;
        int c = (i * 4) % KV_W;
        if (c >= LORA) {
            int s = (i * 4) / KV_W;
            int o = s * DR + (c - LORA);
            ((__half2*)g_Rh)[o / 2]     = a;
            ((__half2*)g_Rh)[o / 2 + 1] = b;
        }
    } else if (i < N1 + N2) {
        int j = i - N1;
        float4 v = ((const float4*)wk)[j];
        __half2 a = __floats2half2_rn(v.x, v.y);
        __half2 b = __floats2half2_rn(v.z, v.w);
        ((__half2*)g_wkh)[2 * j] = a; ((__half2*)g_wkh)[2 * j + 1] = b;
    } else if (i < N1 + N2 + N3) {
        int j = i - N1 - N2;
        float4 v = ((const float4*)wv)[j];
        __half2 a = __floats2half2_rn(v.x, v.y);
        __half2 b = __floats2half2_rn(v.z, v.w);
        ((__half2*)g_wvh)[2 * j] = a; ((__half2*)g_wvh)[2 * j + 1] = b;
    }
}

// ========== fused projection: shares the kv_lora A tile ====================
//  g_K[h,s,:] = kv_lora[s,:] . w_kc[h,:,:]^T   (accK)
//  g_V[h,s,:] = kv_lora[s,:] . w_vc[h,:,:]     (accV)
#define PSTR 80
#define PJ_A  0
#define PJ_BK (128 * PSTR)                  // 10240
#define PJ_BV (2 * 128 * PSTR)              // 20480
#define PJ_BVSTR 272
#define PJ_STAGE (PJ_BV + 32 * PJ_BVSTR)    // 29184
#define PJ_SMEM (2 * PJ_STAGE)              // 58368

__global__ __launch_bounds__(256)
void proj_fused() {
    extern __shared__ __align__(16) char smp[];
    const uint32_t sb = smem_u32(smp);
    const int tid = threadIdx.x, lane = tid & 31, wp = tid >> 5;
    const int grp = lane >> 2, tg = lane & 3;
    const int h = blockIdx.y, s0 = blockIdx.x * 128;

    const __half* Akv = g_kvh + (size_t)s0 * KV_W;
    const __half* BK  = g_wkh + (size_t)h * DKA * LORA;
    const __half* BV  = g_wvh + (size_t)h * LORA * DV;
    const int lr = tid >> 1;
    const int br = tid >> 3, bcb = (tid & 7) * 2;

    #define PJ_LOAD(stage, kt) do { \
        uint32_t base_ = sb + (stage) * PJ_STAGE; \
        _Pragma("unroll") \
        for (int j_ = 0; j_ < 2; j_++) { \
            int c16_ = (tid & 1) * 2 + j_; \
            cp16(base_ + PJ_A  + lr * PSTR + c16_ * 16, Akv + (size_t)lr * KV_W + (kt) + c16_ * 8); \
            cp16(base_ + PJ_BK + lr * PSTR + c16_ * 16, BK  + (size_t)lr * LORA + (kt) + c16_ * 8); \
            int b16_ = bcb + j_; \
            cp16(base_ + PJ_BV + br * PJ_BVSTR + b16_ * 16, BV + (size_t)((kt) + br) * DV + b16_ * 8); \
        } \
    } while (0)

    PJ_LOAD(0, 0); CP_COMMIT();

    float accK[16][4], accV[16][4];
    #pragma unroll
    for (int i = 0; i < 16; i++)
        #pragma unroll
        for (int j = 0; j < 4; j++) { accK[i][j] = 0.f; accV[i][j] = 0.f; }

    const uint32_t aoff  = (uint32_t)((wp * 16 + (lane & 15)) * PSTR + (lane >> 4) * 16);
    const uint32_t bkoff = (uint32_t)(((lane & 7) + ((lane >> 4) & 1) * 8) * PSTR + ((lane >> 3) & 1) * 16);
    const uint32_t bvoff = (uint32_t)(((lane & 7) + ((lane >> 3) & 1) * 8) * PJ_BVSTR + ((lane >> 4) & 1) * 16);

    for (int c = 0; c < 16; c++) {
        if (c + 1 < 16) { PJ_LOAD((c + 1) & 1, (c + 1) * 32); CP_COMMIT(); CP_WAIT1(); }
        else { CP_WAIT0(); }
        __syncthreads();
        const uint32_t base = sb + (c & 1) * PJ_STAGE;
        #pragma unroll
        for (int ks = 0; ks < 2; ks++) {
            uint32_t a[4];
            ldsm4(a, base + PJ_A + aoff + ks * 32);
            #pragma unroll
            for (int np = 0; np < 8; np++) {
                uint32_t bk[4], bv[4];
                ldsm4(bk, base + PJ_BK + bkoff + np * 16 * PSTR + ks * 32);
                mma16816h(accK[np * 2],     a, bk);
                mma16816h(accK[np * 2 + 1], a, bk + 2);
                ldsm4t(bv, base + PJ_BV + bvoff + ks * 16 * PJ_BVSTR + np * 32);
                mma16816h(accV[np * 2],     a, bv);
                mma16816h(accV[np * 2 + 1], a, bv + 2);
            }
        }
        __syncthreads();
    }

    const int r0 = s0 + wp * 16 + grp, r1 = r0 + 8;
    #pragma unroll
    for (int nb = 0; nb < 16; nb++) {
        int col = nb * 8 + tg * 2;
        __half2 k0 = __floats2half2_rn(accK[nb][0], accK[nb][1]);
        __half2 k1 = __floats2half2_rn(accK[nb][2], accK[nb][3]);
        *(__half2*)(g_K + ((size_t)h * SS + r0) * DKA + col) = k0;
        *(__half2*)(g_K + ((size_t)h * SS + r1) * DKA + col) = k1;
        __half2 v0 = __floats2half2_rn(accV[nb][0], accV[nb][1]);
        __half2 v1 = __floats2half2_rn(accV[nb][2], accV[nb][3]);
        *(__half2*)(g_V + ((size_t)h * SS + r0) * DV + col) = v0;
        *(__half2*)(g_V + ((size_t)h * SS + r1) * DV + col) = v1;
    }
}

// ====== attention: 64q CTAs, 4 slots, 1 barrier/tile, fp32 ex2 ==============
#define QROWS 64
#define KSTR2 400
#define VSTR2 304                       // 144 cols (128 V + ones + pad)
#define AT_K 0
#define AT_V (SN * KSTR2)               // 12800
#define AT_STG (AT_V + SN * VSTR2)      // 22528
#define AT_Q (2 * AT_STG)               // Q overlay in slots 2-3 region
#define AT_SMEM (4 * AT_STG)            // 90112

__device__ __forceinline__ void load_stage(uint32_t sb, int h, int s0, int slot, int tid) {
    const uint32_t base = sb + (uint32_t)slot * AT_STG;
    const __half* gk = g_K + ((size_t)h * SS + s0) * DKA;
    const __half* gr = g_Rh + (size_t)s0 * DR;
    const __half* gv = g_V + ((size_t)h * SS + s0) * DV;
    #pragma unroll
    for (int i = 0; i < 6; i++) {
        int idx = tid + i * 128;
        int r = idx / 24, c = idx - r * 24;
        if (c < 16) cp16(base + AT_K + r * KSTR2 + c * 16, gk + (size_t)r * DKA + c * 8);
        else        cp16(base + AT_K + r * KSTR2 + c * 16, gr + (size_t)r * DR + (c - 16) * 8);
    }
    #pragma unroll
    for (int i = 0; i < 4; i++) {
        int idx = tid + i * 128;
        int r = idx >> 4, c = idx & 15;
        cp16(base + AT_V + r * VSTR2 + c * 16, gv + (size_t)r * DV + c * 8);
    }
}

__global__ __launch_bounds__(128, 2)
void attn_mma(const float* __restrict__ q, float* __restrict__ out) {
    extern __shared__ __align__(16) char sma[];
    const uint32_t sb = smem_u32(sma);
    const int tid = threadIdx.x, lane = tid & 31, wp = tid >> 5;
    const int grp = lane >> 2, tg = lane & 3;
    const int h = blockIdx.y, t0 = blockIdx.x * QROWS;

    // slots 0,1 first (independent of Q staging)
    load_stage(sb, h, 0, 0, tid); CP_COMMIT();
    load_stage(sb, h, SN, 1, tid); CP_COMMIT();

    // Q: scale by QSCALE, round fp16, stage in slots 2-3 overlay region
    {
        const int r = tid >> 1, half = tid & 1;
        const float* qp = q + (size_t)(t0 + r) * (HH * (DKA + DR)) + (size_t)h * (DKA + DR) + half * 96;
        uint32_t* pH = (uint32_t*)(sma + AT_Q + r * KSTR2 + half * 192);
        #pragma unroll
        for (int i = 0; i < 24; i++) {
            float4 v = *(const float4*)(qp + i * 4);
            __half2 a = __floats2half2_rn(v.x * QSCALE, v.y * QSCALE);
            __half2 b = __floats2half2_rn(v.z * QSCALE, v.w * QSCALE);
            pH[2 * i]     = *(uint32_t*)&a;
            pH[2 * i + 1] = *(uint32_t*)&b;
        }
    }
    __syncthreads();

    uint32_t qf[12][4];
    {
        const uint32_t qa = sb + AT_Q + (uint32_t)((wp * 16 + (lane & 15)) * KSTR2 + (lane >> 4) * 16);
        #pragma unroll
        for (int ks = 0; ks < 12; ks++) ldsm4(qf[ks], qa + ks * 32);
    }
    // all warps must finish reading Q fragments before the ones-init below
    // overwrites parts of the Q overlay region.
    __syncthreads();

    // ones-column init: all 4 slots, V cols 128..143 (col 128 = 1.0)
    {
        const __half2 one0 = __halves2half2(__float2half(1.f), __float2half(0.f));
        const __half2 zero = __halves2half2(__float2half(0.f), __float2half(0.f));
        #pragma unroll
        for (int i = 0; i < 8; i++) {
            int idx = tid + i * 128;           // 1024 = 4 slots * 32 rows * 8 half2
            int slot = idx >> 8;
            int rem = idx & 255;
            int r = rem >> 3, c2 = rem & 7;
            *(__half2*)(sma + slot * AT_STG + AT_V + r * VSTR2 + 256 + c2 * 4)
                = (c2 == 0) ? one0 : zero;
        }
    }
    __syncthreads();

    load_stage(sb, h, 2 * SN, 2, tid); CP_COMMIT();

    float O[18][4];
    #pragma unroll
    for (int i = 0; i < 18; i++)
        #pragma unroll
        for (int j = 0; j < 4; j++) O[i][j] = 0.f;

    const uint32_t kboff = (uint32_t)(((lane & 7) + ((lane >> 4) & 1) * 8) * KSTR2 + ((lane >> 3) & 1) * 16);
    const uint32_t vboff = (uint32_t)(((lane & 7) + ((lane >> 3) & 1) * 8) * VSTR2 + ((lane >> 4) & 1) * 16);

    for (int t = 0; t < NT; t++) {
        CP_WAIT2();
        __syncthreads();
        const uint32_t base = sb + (uint32_t)(t & 3) * AT_STG;

        // MMA1: scores (log2-domain; QSCALE folded in)
        float S[4][4];
        #pragma unroll
        for (int i = 0; i < 4; i++)
            #pragma unroll
            for (int j = 0; j < 4; j++) S[i][j] = 0.f;

        #pragma unroll
        for (int ks = 0; ks < 12; ks++) {
            #pragma unroll
            for (int np = 0; np < 2; np++) {
                uint32_t b[4];
                ldsm4(b, base + AT_K + kboff + np * 16 * KSTR2 + ks * 32);
                mma16816h(S[np * 2],     qf[ks], b);
                mma16816h(S[np * 2 + 1], qf[ks], b + 2);
            }
        }

        // softmax: p = 2^S in fp32 (MUFU), then pack to fp16 A-fragments
        uint32_t ph[2][4];
        #pragma unroll
        for (int kk = 0; kk < 2; kk++) {
            #pragma unroll
            for (int sub = 0; sub < 2; sub++) {
                float* c = S[2 * kk + sub];
                float e0 = ex2f(c[0]);
                float e1 = ex2f(c[1]);
                float e2 = ex2f(c[2]);
                float e3 = ex2f(c[3]);
                __half2 p0 = __floats2half2_rn(e0, e1);
                __half2 p1 = __floats2half2_rn(e2, e3);
                ph[kk][sub * 2]     = *(uint32_t*)&p0;
                ph[kk][sub * 2 + 1] = *(uint32_t*)&p1;
            }
        }

        // MMA2: O += P * V  (np=8 block carries the ones column -> row sums)
        #pragma unroll
        for (int kk = 0; kk < 2; kk++) {
            #pragma unroll
            for (int np = 0; np < 9; np++) {
                uint32_t v[4];
                ldsm4t(v, base + AT_V + vboff + kk * 16 * VSTR2 + np * 32);
                mma16816h(O[np * 2],     ph[kk], v);
                mma16816h(O[np * 2 + 1], ph[kk], v + 2);
            }
        }
        // no tail barrier: top-of-tile barrier at t proves all warps finished t-1,
        // and slot (t+3)&3 == (t-1)&3 was last read at t-1.
        if (t + 3 < NT) load_stage(sb, h, (t + 3) * SN, (t + 3) & 3, tid);
        CP_COMMIT();
    }

    // row sums from the tensor-core ones-column: block 16, col 128
    const float r0s = __shfl_sync(0xffffffffu, O[16][0], lane & ~3);
    const float r1s = __shfl_sync(0xffffffffu, O[16][2], lane & ~3);
    const float i0 = 1.0f / r0s, i1 = 1.0f / r1s;

    const int r0 = t0 + wp * 16 + grp, r1 = r0 + 8;
    #pragma unroll
    for (int nb = 0; nb < 16; nb++) {
        const int col = h * DV + nb * 8 + tg * 2;
        float2 v0 = make_float2(O[nb][0] * i0, O[nb][1] * i0);
        float2 v1 = make_float2(O[nb][2] * i1, O[nb][3] * i1);
        *(float2*)(out + (size_t)r0 * (HH * DV) + col) = v0;
        *(float2*)(out + (size_t)r1 * (HH * DV) + col) = v1;
    }
}

// ===================== launch =====================
extern "C" void kernel_launch(void* const* d_in, const int* in_sizes, int n_in,
                              void* d_out, int out_size) {
    const float* q    = (const float*)d_in[0];   // (1024, 16, 192)
    const float* kv   = (const float*)d_in[1];   // (8192, 576)
    const float* w_kc = (const float*)d_in[2];   // (16, 128, 512)
    const float* w_vc = (const float*)d_in[3];   // (16, 512, 128)
    float* out = (float*)d_out;                  // (1024, 2048)
    (void)in_sizes; (void)n_in; (void)out_size;

    cudaFuncSetAttribute(proj_fused, cudaFuncAttributeMaxDynamicSharedMemorySize, PJ_SMEM);
    cudaFuncSetAttribute(attn_mma, cudaFuncAttributeMaxDynamicSharedMemorySize, AT_SMEM);

    split_kernel<<<(N1 + N2 + N3 + 255) / 256, 256>>>(kv, w_kc, w_vc);

    dim3 pgrid(SS / 128, HH);
    proj_fused<<<pgrid, 256, PJ_SMEM>>>();

    dim3 agrid(TT / QROWS, HH);   // (16, 16) = 256 CTAs
    attn_mma<<<agrid, 128, AT_SMEM>>>(q, out);
}